// round 12
// baseline (speedup 1.0000x reference)
#include <cuda_runtime.h>
#include <cuda_fp16.h>
#include <stdint.h>
#include <math.h>

// Problem constants
#define Bc 8
#define Nc 32
#define Tc 32
#define Dc 4
#define Kc 2
#define Hc 256
#define Pc 4
#define Ec 992            // N*(N-1) = 32*31
#define TGc 8             // T/P
#define BTc 64            // B*TG
#define ROWS_E (BTc*Ec)   // 63488 = 2048*31

// Output layout (float32)
#define SZ_PRED (Bc*Nc*(Tc-1)*Dc)
#define OFF_REL SZ_PRED
#define SZ_REL (Bc*Ec*Kc)
#define OFF_HOOK (OFF_REL + SZ_REL)

// Device scratch (no allocation; BSS zero-initialized)
__device__ float g_edges[Ec*Kc];
__device__ float g_last[BTc*Nc*Dc];
__device__ float g_agg[2048*Hc];        // 2 MB; invariant: zero at kernel_launch entry
__device__ uint4 g_W2h[16384];          // W2^T fp16 [e][n][k] swizzled 512B rows (256 KB)
__device__ uint4 g_W1h[512];            // W1^T fp16 [e][n][d] 16B rows (8 KB)

// ---------------------------------------------------------------------------
// smem layout for k_edge (110 KB -> 2 CTAs/SM)
#define SM_A    0            // A fp16 one expert: 128 x 512B = 65536
#define SM_B    65536        // B fp16 n-quarter: 64 x 512B = 32768
#define SM_W1H  98304        // W1h fp16 both experts: 8192
#define SM_PMH  106496       // premsg fp16 128 x 16B = 2048
#define SM_B1   108544       // b1 fp32 both: 2048
#define SM_B2   110592       // b2 fp32 both: 2048
#define SMEM_TOTAL 112640

// smem layout for k_node (dynamic, ~54 KB)
#define NSM_AUG   0                       // 16 x 260 f32 = 16640
#define NSM_H1    16640                   // 16 x 260 f32 = 16640
#define NSM_PB    33280                   // 16 x 256 f32 = 16384
#define NSM_LAST  49664                   // 16 x 4 f32 = 256
#define NSM_WO3   49920                   // 1024 f32 = 4096
#define NSM_TOTAL 54016

static __device__ __forceinline__ uint32_t smem_u32(const void* p) {
    uint32_t a;
    asm("{ .reg .u64 t; cvta.to.shared.u64 t, %1; cvt.u32.u64 %0, t; }" : "=r"(a) : "l"(p));
    return a;
}
#define LDMX4(r0,r1,r2,r3,addr) \
    asm volatile("ldmatrix.sync.aligned.m8n8.x4.shared.b16 {%0,%1,%2,%3}, [%4];" \
        : "=r"(r0), "=r"(r1), "=r"(r2), "=r"(r3) : "r"(addr))
#define LDMX2(r0,r1,addr) \
    asm volatile("ldmatrix.sync.aligned.m8n8.x2.shared.b16 {%0,%1}, [%2];" \
        : "=r"(r0), "=r"(r1) : "r"(addr))
#define MMA16816(c,a0,a1,a2,a3,b0,b1) \
    asm volatile("mma.sync.aligned.m16n8k16.row.col.f32.f16.f16.f32 " \
        "{%0,%1,%2,%3}, {%4,%5,%6,%7}, {%8,%9}, {%0,%1,%2,%3};" \
        : "+f"((c)[0]), "+f"((c)[1]), "+f"((c)[2]), "+f"((c)[3]) \
        : "r"(a0), "r"(a1), "r"(a2), "r"(a3), "r"(b0), "r"(b1))
#define MMA16808(c,a0,a1,b0) \
    asm volatile("mma.sync.aligned.m16n8k8.row.col.f32.f16.f16.f32 " \
        "{%0,%1,%2,%3}, {%4,%5}, {%6}, {%0,%1,%2,%3};" \
        : "+f"((c)[0]), "+f"((c)[1]), "+f"((c)[2]), "+f"((c)[3]) \
        : "r"(a0), "r"(a1), "r"(b0))
#define CP16(dst, src) \
    asm volatile("cp.async.cg.shared.global [%0], [%1], 16;" :: "r"(dst), "l"(src) : "memory")
#define CP_COMMIT() asm volatile("cp.async.commit_group;" ::: "memory")
#define CP_WAIT(n)  asm volatile("cp.async.wait_group %0;" :: "n"(n) : "memory")

static __device__ __forceinline__ int swb(int r, int c) {
    return r*512 + (((c >> 3) ^ (r & 7)) << 4) + (c & 7)*2;
}
static __device__ __forceinline__ int sw_off(int row, int kchunk) {
    return row*512 + ((kchunk ^ (row & 7)) << 4);
}

// GEMM pass: m32n32 per warp over M128 x N64(quarter) x K256
static __device__ __forceinline__ void gemm_q(
    float (&acc)[2][4][4],
    uint32_t aBase, uint32_t bBase,
    const uint32_t (&aRow)[2], const uint32_t (&bRow)[2],
    uint32_t aSel, uint32_t bSel)
{
    #pragma unroll
    for (int mi = 0; mi < 2; mi++)
        #pragma unroll
        for (int nj = 0; nj < 4; nj++)
            #pragma unroll
            for (int c = 0; c < 4; c++) acc[mi][nj][c] = 0.f;

    #pragma unroll 4
    for (int kc = 0; kc < 16; kc++) {
        uint32_t af[2][4], bf[2][4];
        #pragma unroll
        for (int mi = 0; mi < 2; mi++) {
            uint32_t chunk = kc*2 + aSel;
            LDMX4(af[mi][0], af[mi][1], af[mi][2], af[mi][3],
                  aBase + (aRow[mi] ^ (chunk << 4)));
        }
        #pragma unroll
        for (int njp = 0; njp < 2; njp++) {
            uint32_t chunk = kc*2 + bSel;
            LDMX4(bf[njp][0], bf[njp][1], bf[njp][2], bf[njp][3],
                  bBase + (bRow[njp] ^ (chunk << 4)));
        }
        #pragma unroll
        for (int mi = 0; mi < 2; mi++)
            #pragma unroll
            for (int njp = 0; njp < 2; njp++) {
                MMA16816(acc[mi][njp*2],   af[mi][0], af[mi][1], af[mi][2], af[mi][3],
                         bf[njp][0], bf[njp][1]);
                MMA16816(acc[mi][njp*2+1], af[mi][0], af[mi][1], af[mi][2], af[mi][3],
                         bf[njp][2], bf[njp][3]);
            }
    }
}

// ---------------------------------------------------------------------------
__global__ void k_setup(const float* __restrict__ rel_graph,
                        const float* __restrict__ gumbel,
                        const float* __restrict__ inputs,
                        float* __restrict__ out)
{
    int i = blockIdx.x * blockDim.x + threadIdx.x;
    int stride = gridDim.x * blockDim.x;
    if (i < Ec) {
        float l0 = (rel_graph[2*i]   + gumbel[2*i])   * 2.0f;
        float l1 = (rel_graph[2*i+1] + gumbel[2*i+1]) * 2.0f;
        float m  = fmaxf(l0, l1);
        float e0 = expf(l0 - m), e1 = expf(l1 - m);
        float inv = 1.0f / (e0 + e1);
        g_edges[2*i]   = e0 * inv;
        g_edges[2*i+1] = e1 * inv;
    }
    for (int j = i; j < Bc*Ec*Kc; j += stride)
        out[OFF_REL + j] = rel_graph[j % (Ec*Kc)];
    for (int j = i; j < BTc*Nc*Dc; j += stride) {
        int d  = j & 3;
        int n  = (j >> 2) & 31;
        int bt = j >> 7;
        int b  = bt >> 3, tg = bt & 7;
        g_last[j] = inputs[((b*Nc + n)*Tc + tg*Pc)*Dc + d];
    }
    for (int j = i; j < 2048*Hc; j += stride) g_agg[j] = 0.f;
}

// ---------------------------------------------------------------------------
__global__ void k_prep(const float* __restrict__ W2, const float* __restrict__ W1)
{
    int g = blockIdx.x * blockDim.x + threadIdx.x;
    if (g < 16384) {
        int ex  = g >> 13;
        int rem = g & 8191;
        int n   = rem >> 5;
        int kg  = (rem & 31) * 8;
        float w[8];
        #pragma unroll
        for (int j = 0; j < 8; j++) w[j] = W2[ex*65536 + (kg + j)*256 + n];
        uint4 pk;
        __half2 h0 = __floats2half2_rn(w[0], w[1]);
        __half2 h1 = __floats2half2_rn(w[2], w[3]);
        __half2 h2 = __floats2half2_rn(w[4], w[5]);
        __half2 h3 = __floats2half2_rn(w[6], w[7]);
        pk.x = *(uint32_t*)&h0; pk.y = *(uint32_t*)&h1;
        pk.z = *(uint32_t*)&h2; pk.w = *(uint32_t*)&h3;
        *(uint4*)((char*)g_W2h + ex*131072 + sw_off(n, kg >> 3)) = pk;
    }
    if (g < 512) {
        int ex = g >> 8, n = g & 255;
        float w[8];
        #pragma unroll
        for (int d = 0; d < 8; d++) w[d] = W1[ex*2048 + d*256 + n];
        uint4 pk;
        __half2 h0 = __floats2half2_rn(w[0], w[1]);
        __half2 h1 = __floats2half2_rn(w[2], w[3]);
        __half2 h2 = __floats2half2_rn(w[4], w[5]);
        __half2 h3 = __floats2half2_rn(w[6], w[7]);
        pk.x = *(uint32_t*)&h0; pk.y = *(uint32_t*)&h1;
        pk.z = *(uint32_t*)&h2; pk.w = *(uint32_t*)&h3;
        g_W1h[g] = pk;
    }
}

// ---------------------------------------------------------------------------
// Edge MLP v2: independent per-expert epilogue (additive g_agg), one-expert A,
// quarter-N B tiles -> 110 KB smem -> 2 CTAs/SM.
// ---------------------------------------------------------------------------
__global__ void __launch_bounds__(256, 2) k_edge(
    const float* __restrict__ b1, const float* __restrict__ b2,
    float* __restrict__ out, int step)
{
    extern __shared__ __align__(1024) char sm[];
    uint32_t sb = smem_u32(sm);
    int tid = threadIdx.x, wid = tid >> 5, lane = tid & 31;
    int mbase = blockIdx.x * 128;

    // async: W1h (group 0), B(e0,q0) (group 1)
    CP16(sb + SM_W1H + tid*16, (const void*)(g_W1h + tid));
    CP16(sb + SM_W1H + 4096 + tid*16, (const void*)(g_W1h + 256 + tid));
    CP_COMMIT();
    {
        const uint4* src = g_W2h;   // e=0, q=0
        uint32_t dst = sb + SM_B + tid*16;
        #pragma unroll
        for (int i = 0; i < 8; i++) CP16(dst + i*4096, (const void*)(src + tid + i*256));
    }
    CP_COMMIT();

    {
        float* d1 = (float*)(sm + SM_B1);
        float* d2 = (float*)(sm + SM_B2);
        d1[tid] = b1[tid]; d1[tid+256] = b1[tid+256];
        d2[tid] = b2[tid]; d2[tid+256] = b2[tid+256];
    }
    if (tid < 128) {
        int grow = mbase + tid;
        int bt = grow / Ec, e = grow - bt*Ec;
        int r  = e / (Nc-1), j = e - r*(Nc-1);
        int s  = j + (j >= r);
        float4 a = *(const float4*)(g_last + (bt*Nc + s)*Dc);
        float4 b = *(const float4*)(g_last + (bt*Nc + r)*Dc);
        uint4 pk;
        __half2 h0 = __floats2half2_rn(a.x, a.y);
        __half2 h1 = __floats2half2_rn(a.z, a.w);
        __half2 h2 = __floats2half2_rn(b.x, b.y);
        __half2 h3 = __floats2half2_rn(b.z, b.w);
        pk.x = *(uint32_t*)&h0; pk.y = *(uint32_t*)&h1;
        pk.z = *(uint32_t*)&h2; pk.w = *(uint32_t*)&h3;
        *(uint4*)(sm + SM_PMH + tid*16) = pk;
    }

    CP_WAIT(1);          // W1h ready
    __syncthreads();

    // warp tiling constants: 4 m-warps (m32) x 2 n-warps (n32 of 64-quarter)
    int wm = wid & 3, wn = wid >> 2;
    int lrow = lane >> 2, lane4 = lane & 3;

    uint32_t aRow[2], bRow[2];
    #pragma unroll
    for (int mi = 0; mi < 2; mi++) {
        int row = wm*32 + mi*16 + (lane & 15);
        aRow[mi] = row*512 + ((row & 7) << 4);
    }
    #pragma unroll
    for (int njp = 0; njp < 2; njp++) {
        int row = wn*32 + njp*16 + ((lane >> 4) << 3) + (lane & 7);
        bRow[njp] = row*512 + ((row & 7) << 4);
    }
    uint32_t aSel = lane >> 4, bSel = (lane >> 3) & 1;

    float e0v[4], e1v[4]; int hookr[4];
    #pragma unroll
    for (int qq = 0; qq < 4; qq++) {
        int mi = qq >> 1, rg = qq & 1;
        int grow = mbase + wm*32 + mi*16 + rg*8 + lrow;
        int bt = grow / Ec, eG = grow - bt*Ec;
        e0v[qq] = g_edges[2*eG];
        e1v[qq] = g_edges[2*eG+1];
        int bb = bt >> 3, tg = bt & 7;
        hookr[qq] = ((step*TGc + tg)*Bc + bb)*Ec + eG;
    }
    int gs   = mbase + wm*32;
    int G0   = gs / 31;
    int bnd  = 31 - (gs - G0*31);

    const float* b2s = (const float*)(sm + SM_B2);

    #pragma unroll
    for (int e = 0; e < 2; e++) {
        // ---- build A(e) via mma.m16n8k8 ----
        {
            int m0 = wid * 16;
            uint32_t a0, a1;
            LDMX2(a0, a1, sb + SM_PMH + (m0 + (lane & 15))*16);
            const float* b1e = (const float*)(sm + SM_B1) + e*256;
            #pragma unroll
            for (int nc = 0; nc < 8; nc++) {
                uint32_t bf[4];
                LDMX4(bf[0], bf[1], bf[2], bf[3],
                      sb + SM_W1H + e*4096 + (nc*32 + lane)*16);
                #pragma unroll
                for (int c = 0; c < 4; c++) {
                    float acc[4] = {0.f, 0.f, 0.f, 0.f};
                    MMA16808(acc, a0, a1, bf[c]);
                    int col = nc*32 + c*8 + (lane & 3)*2;
                    float bx = b1e[col], by = b1e[col+1];
                    __half2 v0 = __floats2half2_rn(fmaxf(acc[0]+bx, 0.f), fmaxf(acc[1]+by, 0.f));
                    __half2 v1 = __floats2half2_rn(fmaxf(acc[2]+bx, 0.f), fmaxf(acc[3]+by, 0.f));
                    int r0 = m0 + (lane >> 2), r1 = r0 + 8;
                    *(__half2*)(sm + SM_A + swb(r0, col)) = v0;
                    *(__half2*)(sm + SM_A + swb(r1, col)) = v1;
                }
            }
        }
        CP_WAIT(0);        // B(e, 0) ready
        __syncthreads();   // A(e) + B visible

        #pragma unroll
        for (int q = 0; q < 4; q++) {
            float acc[2][4][4];
            gemm_q(acc, sb + SM_A, sb + SM_B, aRow, bRow, aSel, bSel);
            __syncthreads();   // all warps done reading SM_B

            // prefetch next B tile into SM_B (overlaps epilogue)
            if (q < 3 || e == 0) {
                int ne = (q < 3) ? e : 1;
                int nq = (q < 3) ? q + 1 : 0;
                const uint4* src = g_W2h + ne*8192 + nq*2048;
                uint32_t dst = sb + SM_B + tid*16;
                #pragma unroll
                for (int i = 0; i < 8; i++) CP16(dst + i*4096, (const void*)(src + tid + i*256));
            }
            CP_COMMIT();

            // ---- epilogue(e, q): scale, hooks (e==1), segmented agg atomics ----
            #pragma unroll
            for (int nj = 0; nj < 4; nj++) {
                int cg = q*64 + wn*32 + nj*8 + lane4*2;
                float bx = b2s[e*256 + cg], by = b2s[e*256 + cg + 1];
                float pA0 = 0.f, pA1 = 0.f, pB0 = 0.f, pB1 = 0.f;
                #pragma unroll
                for (int mi = 0; mi < 2; mi++)
                    #pragma unroll
                    for (int rg = 0; rg < 2; rg++) {
                        int ridx = mi*2 + rg;
                        float sc = e ? e1v[ridx] : e0v[ridx];
                        float v0 = fmaxf(acc[mi][nj][rg*2]   + bx, 0.f) * sc;
                        float v1 = fmaxf(acc[mi][nj][rg*2+1] + by, 0.f) * sc;
                        if (e == 1)
                            *(float2*)(out + OFF_HOOK + (size_t)hookr[ridx]*Hc + cg) =
                                make_float2(v0, v1);
                        int rel = mi*16 + rg*8 + lrow;
                        if (rel < bnd) { pA0 += v0; pA1 += v1; }
                        else           { pB0 += v0; pB1 += v1; }
                    }
                #pragma unroll
                for (int d = 4; d <= 16; d <<= 1) {
                    pA0 += __shfl_xor_sync(0xffffffffu, pA0, d);
                    pA1 += __shfl_xor_sync(0xffffffffu, pA1, d);
                    pB0 += __shfl_xor_sync(0xffffffffu, pB0, d);
                    pB1 += __shfl_xor_sync(0xffffffffu, pB1, d);
                }
                if (lane < 4) {
                    atomicAdd(g_agg + (size_t)G0*Hc + cg,         pA0);
                    atomicAdd(g_agg + (size_t)G0*Hc + cg + 1,     pA1);
                    atomicAdd(g_agg + (size_t)(G0+1)*Hc + cg,     pB0);
                    atomicAdd(g_agg + (size_t)(G0+1)*Hc + cg + 1, pB1);
                }
            }
            CP_WAIT(0);
            __syncthreads();   // next B ready; SM_A rebuild (e=1) safe after this
        }
    }
}

// ---------------------------------------------------------------------------
// Node MLP v5: 128 blocks x 1024 threads, 16 rows/block (single wave).
// c = tid&255, jh = (tid>>8)&1 splits reduction dim, rg = tid>>9 splits rows.
// jh=1 writes partials to smem; jh=0 combines. Reads + zeroes g_agg.
// ---------------------------------------------------------------------------
__global__ void __launch_bounds__(1024) k_node(
    const float* __restrict__ Wo1, const float* __restrict__ bo1,
    const float* __restrict__ Wo2, const float* __restrict__ bo2,
    const float* __restrict__ Wo3, const float* __restrict__ bo3,
    float* __restrict__ out, int step)
{
    extern __shared__ __align__(16) char nsm[];
    float* augS  = (float*)(nsm + NSM_AUG);    // [16][260]
    float* h1S   = (float*)(nsm + NSM_H1);     // [16][260]
    float* pbS   = (float*)(nsm + NSM_PB);     // [16][256]
    float* lastS = (float*)(nsm + NSM_LAST);   // [16][4]
    float* wo3S  = (float*)(nsm + NSM_WO3);    // [1024]

    int tid = threadIdx.x;
    int wid = tid >> 5, lane = tid & 31;
    int base_row = blockIdx.x * 16;
    int c  = tid & 255;
    int jh = (tid >> 8) & 1;
    int rg = tid >> 9;               // row group: rows rg*8 .. rg*8+7

    wo3S[tid] = Wo3[tid];
    if (tid < 64) {
        int n = tid >> 2, d = tid & 3;
        float v = g_last[(base_row + n)*Dc + d];
        lastS[n*4 + d] = v;
        augS[n*260 + d] = v;
    }
    if (wid < 16) {   // agg read + zero: warp wid owns row wid
        float* src = g_agg + (size_t)(base_row + wid)*Hc + lane*8;
        float4 v0 = *(float4*)src, v1 = *(float4*)(src + 4);
        *(float4*)(&augS[wid*260 + 4 + lane*8])     = v0;
        *(float4*)(&augS[wid*260 + 4 + lane*8 + 4]) = v1;
        float4 z = make_float4(0.f, 0.f, 0.f, 0.f);
        *(float4*)src = z; *(float4*)(src + 4) = z;
    }
    __syncthreads();

    // Layer 1: jh=0 covers j[0,132), jh=1 covers j[132,260); rows rg*8..+7
    float acc[8];
    {
        #pragma unroll
        for (int r = 0; r < 8; r++) acc[r] = 0.f;
        const float* aug0 = augS + (rg*8)*260;
        if (jh == 0) {
            #pragma unroll 8
            for (int j0 = 0; j0 < 132; j0 += 4) {
                float w0 = Wo1[(j0+0)*Hc + c];
                float w1 = Wo1[(j0+1)*Hc + c];
                float w2 = Wo1[(j0+2)*Hc + c];
                float w3 = Wo1[(j0+3)*Hc + c];
                #pragma unroll
                for (int r = 0; r < 8; r++) {
                    float4 av = *(const float4*)(aug0 + r*260 + j0);
                    acc[r] += av.x*w0 + av.y*w1 + av.z*w2 + av.w*w3;
                }
            }
        } else {
            #pragma unroll 8
            for (int j0 = 132; j0 < 260; j0 += 4) {
                float w0 = Wo1[(j0+0)*Hc + c];
                float w1 = Wo1[(j0+1)*Hc + c];
                float w2 = Wo1[(j0+2)*Hc + c];
                float w3 = Wo1[(j0+3)*Hc + c];
                #pragma unroll
                for (int r = 0; r < 8; r++) {
                    float4 av = *(const float4*)(aug0 + r*260 + j0);
                    acc[r] += av.x*w0 + av.y*w1 + av.z*w2 + av.w*w3;
                }
            }
            #pragma unroll
            for (int r = 0; r < 8; r++) pbS[(rg*8 + r)*256 + c] = acc[r];
        }
    }
    __syncthreads();
    if (jh == 0) {
        float bb = bo1[c];
        #pragma unroll
        for (int r = 0; r < 8; r++)
            h1S[(rg*8 + r)*260 + c] =
                fmaxf(acc[r] + pbS[(rg*8 + r)*256 + c] + bb, 0.f);
    }
    __syncthreads();

    // Layer 2: jh=0 covers j[0,128), jh=1 covers j[128,256)
    {
        #pragma unroll
        for (int r = 0; r < 8; r++) acc[r] = 0.f;
        const float* h10 = h1S + (rg*8)*260;
        int jb = jh * 128;
        #pragma unroll 8
        for (int jj = 0; jj < 128; jj += 4) {
            int j0 = jb + jj;
            float w0 = Wo2[(j0+0)*Hc + c];
            float w1 = Wo2[(j0+1)*Hc + c];
            float w2 = Wo2[(j0+2)*Hc + c];
            float w3 = Wo2[(j0+3)*Hc + c];
            #pragma unroll
            for (int r = 0; r < 8; r++) {
                float4 av = *(const float4*)(h10 + r*260 + j0);
                acc[r] += av.x*w0 + av.y*w1 + av.z*w2 + av.w*w3;
            }
        }
        if (jh == 1) {
            #pragma unroll
            for (int r = 0; r < 8; r++) pbS[(rg*8 + r)*256 + c] = acc[r];
        }
    }
    __syncthreads();
    if (jh == 0) {
        float bb = bo2[c];
        #pragma unroll
        for (int r = 0; r < 8; r++)
            augS[(rg*8 + r)*260 + 4 + c] =
                fmaxf(acc[r] + pbS[(rg*8 + r)*256 + c] + bb, 0.f);
    }
    __syncthreads();

    // Layer 3 (256->4) + residual + writes
    if (tid < 64) {
        int n = tid >> 2, d = tid & 3;
        float v = bo3[d];
        #pragma unroll 8
        for (int cc = 0; cc < Hc; cc++)
            v += augS[n*260 + 4 + cc] * wo3S[cc*Dc + d];
        float nl = lastS[n*4 + d] + v;
        int grow = base_row + n;
        g_last[grow*Dc + d] = nl;
        int bt = grow >> 5, gn = grow & 31;
        int b = bt >> 3, tg = bt & 7;
        int t = tg*Pc + step;
        if (t < Tc - 1)
            out[((b*Nc + gn)*(Tc-1) + t)*Dc + d] = nl;
    }
}

// ---------------------------------------------------------------------------
extern "C" void kernel_launch(void* const* d_in, const int* in_sizes, int n_in,
                              void* d_out, int out_size)
{
    const float* inputs    = (const float*)d_in[0];
    const float* rel_graph = (const float*)d_in[1];
    const float* W1  = (const float*)d_in[2];
    const float* b1  = (const float*)d_in[3];
    const float* W2  = (const float*)d_in[4];
    const float* b2  = (const float*)d_in[5];
    const float* Wo1 = (const float*)d_in[6];
    const float* bo1 = (const float*)d_in[7];
    const float* Wo2 = (const float*)d_in[8];
    const float* bo2 = (const float*)d_in[9];
    const float* Wo3 = (const float*)d_in[10];
    const float* bo3 = (const float*)d_in[11];
    const float* gumbel = (const float*)d_in[14];
    float* out = (float*)d_out;

    cudaFuncSetAttribute(k_edge, cudaFuncAttributeMaxDynamicSharedMemorySize, SMEM_TOTAL);
    cudaFuncSetAttribute(k_node, cudaFuncAttributeMaxDynamicSharedMemorySize, NSM_TOTAL);

    k_setup<<<128, 256>>>(rel_graph, gumbel, inputs, out);
    k_prep<<<64, 256>>>(W2, W1);
    for (int p = 0; p < Pc; p++) {
        k_edge<<<ROWS_E/128, 256, SMEM_TOTAL>>>(b1, b2, out, p);
        k_node<<<128, 1024, NSM_TOTAL>>>(Wo1, bo1, Wo2, bo2, Wo3, bo3, out, p);
    }
}

// round 13
// speedup vs baseline: 1.0250x; 1.0250x over previous
#include <cuda_runtime.h>
#include <cuda_fp16.h>
#include <stdint.h>
#include <math.h>

// Problem constants
#define Bc 8
#define Nc 32
#define Tc 32
#define Dc 4
#define Kc 2
#define Hc 256
#define Pc 4
#define Ec 992            // N*(N-1) = 32*31
#define TGc 8             // T/P
#define BTc 64            // B*TG
#define ROWS_E (BTc*Ec)   // 63488 = 2048*31

// Output layout (float32)
#define SZ_PRED (Bc*Nc*(Tc-1)*Dc)
#define OFF_REL SZ_PRED
#define SZ_REL (Bc*Ec*Kc)
#define OFF_HOOK (OFF_REL + SZ_REL)

// Device scratch (no allocation; BSS zero-initialized)
__device__ float g_edges[Ec*Kc];
__device__ float g_last[BTc*Nc*Dc];
__device__ float g_agg[2048*Hc];        // 2 MB; invariant: zero at kernel_launch entry
__device__ uint4 g_W2h[16384];          // W2^T fp16 [e][n][k] swizzled 512B rows (256 KB)
__device__ uint4 g_W1h[512];            // W1^T fp16 [e][n][d] 16B rows (8 KB)
__device__ float g_Wo1B[65*1024];       // Wo1 blocked [j/4][c][4] fp32 (260 KB)
__device__ float g_Wo2B[64*1024];       // Wo2 blocked [j/4][c][4] fp32 (256 KB)

// ---------------------------------------------------------------------------
// smem layout for k_edge (110 KB -> 2 CTAs/SM)
#define SM_A    0            // A fp16 one expert: 128 x 512B = 65536
#define SM_B    65536        // B fp16 n-quarter: 64 x 512B = 32768
#define SM_W1H  98304        // W1h fp16 both experts: 8192
#define SM_PMH  106496       // premsg fp16 128 x 16B = 2048
#define SM_B1   108544       // b1 fp32 both: 2048
#define SM_B2   110592       // b2 fp32 both: 2048
#define SMEM_TOTAL 112640

static __device__ __forceinline__ uint32_t smem_u32(const void* p) {
    uint32_t a;
    asm("{ .reg .u64 t; cvta.to.shared.u64 t, %1; cvt.u32.u64 %0, t; }" : "=r"(a) : "l"(p));
    return a;
}
#define LDMX4(r0,r1,r2,r3,addr) \
    asm volatile("ldmatrix.sync.aligned.m8n8.x4.shared.b16 {%0,%1,%2,%3}, [%4];" \
        : "=r"(r0), "=r"(r1), "=r"(r2), "=r"(r3) : "r"(addr))
#define LDMX2(r0,r1,addr) \
    asm volatile("ldmatrix.sync.aligned.m8n8.x2.shared.b16 {%0,%1}, [%2];" \
        : "=r"(r0), "=r"(r1) : "r"(addr))
#define MMA16816(c,a0,a1,a2,a3,b0,b1) \
    asm volatile("mma.sync.aligned.m16n8k16.row.col.f32.f16.f16.f32 " \
        "{%0,%1,%2,%3}, {%4,%5,%6,%7}, {%8,%9}, {%0,%1,%2,%3};" \
        : "+f"((c)[0]), "+f"((c)[1]), "+f"((c)[2]), "+f"((c)[3]) \
        : "r"(a0), "r"(a1), "r"(a2), "r"(a3), "r"(b0), "r"(b1))
#define MMA16808(c,a0,a1,b0) \
    asm volatile("mma.sync.aligned.m16n8k8.row.col.f32.f16.f16.f32 " \
        "{%0,%1,%2,%3}, {%4,%5}, {%6}, {%0,%1,%2,%3};" \
        : "+f"((c)[0]), "+f"((c)[1]), "+f"((c)[2]), "+f"((c)[3]) \
        : "r"(a0), "r"(a1), "r"(b0))
#define CP16(dst, src) \
    asm volatile("cp.async.cg.shared.global [%0], [%1], 16;" :: "r"(dst), "l"(src) : "memory")
#define CP_COMMIT() asm volatile("cp.async.commit_group;" ::: "memory")
#define CP_WAIT(n)  asm volatile("cp.async.wait_group %0;" :: "n"(n) : "memory")

static __device__ __forceinline__ int swb(int r, int c) {
    return r*512 + (((c >> 3) ^ (r & 7)) << 4) + (c & 7)*2;
}
static __device__ __forceinline__ int sw_off(int row, int kchunk) {
    return row*512 + ((kchunk ^ (row & 7)) << 4);
}

// GEMM pass: m32n32 per warp over M128 x N64(quarter) x K256
static __device__ __forceinline__ void gemm_q(
    float (&acc)[2][4][4],
    uint32_t aBase, uint32_t bBase,
    const uint32_t (&aRow)[2], const uint32_t (&bRow)[2],
    uint32_t aSel, uint32_t bSel)
{
    #pragma unroll
    for (int mi = 0; mi < 2; mi++)
        #pragma unroll
        for (int nj = 0; nj < 4; nj++)
            #pragma unroll
            for (int c = 0; c < 4; c++) acc[mi][nj][c] = 0.f;

    #pragma unroll 4
    for (int kc = 0; kc < 16; kc++) {
        uint32_t af[2][4], bf[2][4];
        #pragma unroll
        for (int mi = 0; mi < 2; mi++) {
            uint32_t chunk = kc*2 + aSel;
            LDMX4(af[mi][0], af[mi][1], af[mi][2], af[mi][3],
                  aBase + (aRow[mi] ^ (chunk << 4)));
        }
        #pragma unroll
        for (int njp = 0; njp < 2; njp++) {
            uint32_t chunk = kc*2 + bSel;
            LDMX4(bf[njp][0], bf[njp][1], bf[njp][2], bf[njp][3],
                  bBase + (bRow[njp] ^ (chunk << 4)));
        }
        #pragma unroll
        for (int mi = 0; mi < 2; mi++)
            #pragma unroll
            for (int njp = 0; njp < 2; njp++) {
                MMA16816(acc[mi][njp*2],   af[mi][0], af[mi][1], af[mi][2], af[mi][3],
                         bf[njp][0], bf[njp][1]);
                MMA16816(acc[mi][njp*2+1], af[mi][0], af[mi][1], af[mi][2], af[mi][3],
                         bf[njp][2], bf[njp][3]);
            }
    }
}

// ---------------------------------------------------------------------------
__global__ void k_setup(const float* __restrict__ rel_graph,
                        const float* __restrict__ gumbel,
                        const float* __restrict__ inputs,
                        float* __restrict__ out)
{
    int i = blockIdx.x * blockDim.x + threadIdx.x;
    int stride = gridDim.x * blockDim.x;
    if (i < Ec) {
        float l0 = (rel_graph[2*i]   + gumbel[2*i])   * 2.0f;
        float l1 = (rel_graph[2*i+1] + gumbel[2*i+1]) * 2.0f;
        float m  = fmaxf(l0, l1);
        float e0 = expf(l0 - m), e1 = expf(l1 - m);
        float inv = 1.0f / (e0 + e1);
        g_edges[2*i]   = e0 * inv;
        g_edges[2*i+1] = e1 * inv;
    }
    for (int j = i; j < Bc*Ec*Kc; j += stride)
        out[OFF_REL + j] = rel_graph[j % (Ec*Kc)];
    for (int j = i; j < BTc*Nc*Dc; j += stride) {
        int d  = j & 3;
        int n  = (j >> 2) & 31;
        int bt = j >> 7;
        int b  = bt >> 3, tg = bt & 7;
        g_last[j] = inputs[((b*Nc + n)*Tc + tg*Pc)*Dc + d];
    }
    for (int j = i; j < 2048*Hc; j += stride) g_agg[j] = 0.f;
}

// ---------------------------------------------------------------------------
__global__ void k_prep(const float* __restrict__ W2, const float* __restrict__ W1,
                       const float* __restrict__ Wo1, const float* __restrict__ Wo2)
{
    int g = blockIdx.x * blockDim.x + threadIdx.x;
    int stride = gridDim.x * blockDim.x;
    if (g < 16384) {
        int ex  = g >> 13;
        int rem = g & 8191;
        int n   = rem >> 5;
        int kg  = (rem & 31) * 8;
        float w[8];
        #pragma unroll
        for (int j = 0; j < 8; j++) w[j] = W2[ex*65536 + (kg + j)*256 + n];
        uint4 pk;
        __half2 h0 = __floats2half2_rn(w[0], w[1]);
        __half2 h1 = __floats2half2_rn(w[2], w[3]);
        __half2 h2 = __floats2half2_rn(w[4], w[5]);
        __half2 h3 = __floats2half2_rn(w[6], w[7]);
        pk.x = *(uint32_t*)&h0; pk.y = *(uint32_t*)&h1;
        pk.z = *(uint32_t*)&h2; pk.w = *(uint32_t*)&h3;
        *(uint4*)((char*)g_W2h + ex*131072 + sw_off(n, kg >> 3)) = pk;
    }
    if (g < 512) {
        int ex = g >> 8, n = g & 255;
        float w[8];
        #pragma unroll
        for (int d = 0; d < 8; d++) w[d] = W1[ex*2048 + d*256 + n];
        uint4 pk;
        __half2 h0 = __floats2half2_rn(w[0], w[1]);
        __half2 h1 = __floats2half2_rn(w[2], w[3]);
        __half2 h2 = __floats2half2_rn(w[4], w[5]);
        __half2 h3 = __floats2half2_rn(w[6], w[7]);
        pk.x = *(uint32_t*)&h0; pk.y = *(uint32_t*)&h1;
        pk.z = *(uint32_t*)&h2; pk.w = *(uint32_t*)&h3;
        g_W1h[g] = pk;
    }
    // Node weights, blocked transpose: Wo1B[j/4][c][4], Wo2B[j/4][c][4]
    for (int idx = g; idx < 65*256; idx += stride) {
        int jg = idx >> 8, c = idx & 255;
        float4 w;
        w.x = Wo1[(jg*4+0)*Hc + c];
        w.y = Wo1[(jg*4+1)*Hc + c];
        w.z = Wo1[(jg*4+2)*Hc + c];
        w.w = Wo1[(jg*4+3)*Hc + c];
        *(float4*)(g_Wo1B + jg*1024 + c*4) = w;
    }
    for (int idx = g; idx < 64*256; idx += stride) {
        int jg = idx >> 8, c = idx & 255;
        float4 w;
        w.x = Wo2[(jg*4+0)*Hc + c];
        w.y = Wo2[(jg*4+1)*Hc + c];
        w.z = Wo2[(jg*4+2)*Hc + c];
        w.w = Wo2[(jg*4+3)*Hc + c];
        *(float4*)(g_Wo2B + jg*1024 + c*4) = w;
    }
}

// ---------------------------------------------------------------------------
// Edge MLP v2 (unchanged): per-expert epilogue, one-expert A, quarter-N B.
// ---------------------------------------------------------------------------
__global__ void __launch_bounds__(256, 2) k_edge(
    const float* __restrict__ b1, const float* __restrict__ b2,
    float* __restrict__ out, int step)
{
    extern __shared__ __align__(1024) char sm[];
    uint32_t sb = smem_u32(sm);
    int tid = threadIdx.x, wid = tid >> 5, lane = tid & 31;
    int mbase = blockIdx.x * 128;

    CP16(sb + SM_W1H + tid*16, (const void*)(g_W1h + tid));
    CP16(sb + SM_W1H + 4096 + tid*16, (const void*)(g_W1h + 256 + tid));
    CP_COMMIT();
    {
        const uint4* src = g_W2h;   // e=0, q=0
        uint32_t dst = sb + SM_B + tid*16;
        #pragma unroll
        for (int i = 0; i < 8; i++) CP16(dst + i*4096, (const void*)(src + tid + i*256));
    }
    CP_COMMIT();

    {
        float* d1 = (float*)(sm + SM_B1);
        float* d2 = (float*)(sm + SM_B2);
        d1[tid] = b1[tid]; d1[tid+256] = b1[tid+256];
        d2[tid] = b2[tid]; d2[tid+256] = b2[tid+256];
    }
    if (tid < 128) {
        int grow = mbase + tid;
        int bt = grow / Ec, e = grow - bt*Ec;
        int r  = e / (Nc-1), j = e - r*(Nc-1);
        int s  = j + (j >= r);
        float4 a = *(const float4*)(g_last + (bt*Nc + s)*Dc);
        float4 b = *(const float4*)(g_last + (bt*Nc + r)*Dc);
        uint4 pk;
        __half2 h0 = __floats2half2_rn(a.x, a.y);
        __half2 h1 = __floats2half2_rn(a.z, a.w);
        __half2 h2 = __floats2half2_rn(b.x, b.y);
        __half2 h3 = __floats2half2_rn(b.z, b.w);
        pk.x = *(uint32_t*)&h0; pk.y = *(uint32_t*)&h1;
        pk.z = *(uint32_t*)&h2; pk.w = *(uint32_t*)&h3;
        *(uint4*)(sm + SM_PMH + tid*16) = pk;
    }

    CP_WAIT(1);
    __syncthreads();

    int wm = wid & 3, wn = wid >> 2;
    int lrow = lane >> 2, lane4 = lane & 3;

    uint32_t aRow[2], bRow[2];
    #pragma unroll
    for (int mi = 0; mi < 2; mi++) {
        int row = wm*32 + mi*16 + (lane & 15);
        aRow[mi] = row*512 + ((row & 7) << 4);
    }
    #pragma unroll
    for (int njp = 0; njp < 2; njp++) {
        int row = wn*32 + njp*16 + ((lane >> 4) << 3) + (lane & 7);
        bRow[njp] = row*512 + ((row & 7) << 4);
    }
    uint32_t aSel = lane >> 4, bSel = (lane >> 3) & 1;

    float e0v[4], e1v[4]; int hookr[4];
    #pragma unroll
    for (int qq = 0; qq < 4; qq++) {
        int mi = qq >> 1, rg = qq & 1;
        int grow = mbase + wm*32 + mi*16 + rg*8 + lrow;
        int bt = grow / Ec, eG = grow - bt*Ec;
        e0v[qq] = g_edges[2*eG];
        e1v[qq] = g_edges[2*eG+1];
        int bb = bt >> 3, tg = bt & 7;
        hookr[qq] = ((step*TGc + tg)*Bc + bb)*Ec + eG;
    }
    int gs   = mbase + wm*32;
    int G0   = gs / 31;
    int bnd  = 31 - (gs - G0*31);

    const float* b2s = (const float*)(sm + SM_B2);

    #pragma unroll
    for (int e = 0; e < 2; e++) {
        {
            int m0 = wid * 16;
            uint32_t a0, a1;
            LDMX2(a0, a1, sb + SM_PMH + (m0 + (lane & 15))*16);
            const float* b1e = (const float*)(sm + SM_B1) + e*256;
            #pragma unroll
            for (int nc = 0; nc < 8; nc++) {
                uint32_t bf[4];
                LDMX4(bf[0], bf[1], bf[2], bf[3],
                      sb + SM_W1H + e*4096 + (nc*32 + lane)*16);
                #pragma unroll
                for (int c = 0; c < 4; c++) {
                    float acc[4] = {0.f, 0.f, 0.f, 0.f};
                    MMA16808(acc, a0, a1, bf[c]);
                    int col = nc*32 + c*8 + (lane & 3)*2;
                    float bx = b1e[col], by = b1e[col+1];
                    __half2 v0 = __floats2half2_rn(fmaxf(acc[0]+bx, 0.f), fmaxf(acc[1]+by, 0.f));
                    __half2 v1 = __floats2half2_rn(fmaxf(acc[2]+bx, 0.f), fmaxf(acc[3]+by, 0.f));
                    int r0 = m0 + (lane >> 2), r1 = r0 + 8;
                    *(__half2*)(sm + SM_A + swb(r0, col)) = v0;
                    *(__half2*)(sm + SM_A + swb(r1, col)) = v1;
                }
            }
        }
        CP_WAIT(0);
        __syncthreads();

        #pragma unroll
        for (int q = 0; q < 4; q++) {
            float acc[2][4][4];
            gemm_q(acc, sb + SM_A, sb + SM_B, aRow, bRow, aSel, bSel);
            __syncthreads();

            if (q < 3 || e == 0) {
                int ne = (q < 3) ? e : 1;
                int nq = (q < 3) ? q + 1 : 0;
                const uint4* src = g_W2h + ne*8192 + nq*2048;
                uint32_t dst = sb + SM_B + tid*16;
                #pragma unroll
                for (int i = 0; i < 8; i++) CP16(dst + i*4096, (const void*)(src + tid + i*256));
            }
            CP_COMMIT();

            #pragma unroll
            for (int nj = 0; nj < 4; nj++) {
                int cg = q*64 + wn*32 + nj*8 + lane4*2;
                float bx = b2s[e*256 + cg], by = b2s[e*256 + cg + 1];
                float pA0 = 0.f, pA1 = 0.f, pB0 = 0.f, pB1 = 0.f;
                #pragma unroll
                for (int mi = 0; mi < 2; mi++)
                    #pragma unroll
                    for (int rg = 0; rg < 2; rg++) {
                        int ridx = mi*2 + rg;
                        float sc = e ? e1v[ridx] : e0v[ridx];
                        float v0 = fmaxf(acc[mi][nj][rg*2]   + bx, 0.f) * sc;
                        float v1 = fmaxf(acc[mi][nj][rg*2+1] + by, 0.f) * sc;
                        if (e == 1)
                            *(float2*)(out + OFF_HOOK + (size_t)hookr[ridx]*Hc + cg) =
                                make_float2(v0, v1);
                        int rel = mi*16 + rg*8 + lrow;
                        if (rel < bnd) { pA0 += v0; pA1 += v1; }
                        else           { pB0 += v0; pB1 += v1; }
                    }
                #pragma unroll
                for (int d = 4; d <= 16; d <<= 1) {
                    pA0 += __shfl_xor_sync(0xffffffffu, pA0, d);
                    pA1 += __shfl_xor_sync(0xffffffffu, pA1, d);
                    pB0 += __shfl_xor_sync(0xffffffffu, pB0, d);
                    pB1 += __shfl_xor_sync(0xffffffffu, pB1, d);
                }
                if (lane < 4) {
                    atomicAdd(g_agg + (size_t)G0*Hc + cg,         pA0);
                    atomicAdd(g_agg + (size_t)G0*Hc + cg + 1,     pA1);
                    atomicAdd(g_agg + (size_t)(G0+1)*Hc + cg,     pB0);
                    atomicAdd(g_agg + (size_t)(G0+1)*Hc + cg + 1, pB1);
                }
            }
            CP_WAIT(0);
            __syncthreads();
        }
    }
}

// ---------------------------------------------------------------------------
// Node MLP (R9 j-split, blocked-transposed weights): 512 threads, 2 threads
// per output col split the reduction; LDG.128 coalesced weight loads.
// ---------------------------------------------------------------------------
__global__ void __launch_bounds__(512) k_node(
    const float* __restrict__ bo1, const float* __restrict__ bo2,
    const float* __restrict__ Wo3, const float* __restrict__ bo3,
    float* __restrict__ out, int step)
{
    __shared__ float augS[8][264];
    __shared__ float h1S[8][264];
    __shared__ float pbS[16][260];   // partial sums [jh*8+r][c]
    __shared__ float lastS[8][4];
    __shared__ float wo3S[Hc*Dc];

    int tid = threadIdx.x;
    int wid = tid >> 5, lane = tid & 31;
    int base_row = blockIdx.x * 8;
    int c  = tid & 255;        // output column
    int jh = tid >> 8;         // reduction half (warp-uniform)

    for (int i = tid; i < Hc*Dc; i += 512) wo3S[i] = Wo3[i];
    if (tid < 32) {
        int n = tid >> 2, d = tid & 3;
        float v = g_last[(base_row + n)*Dc + d];
        lastS[n][d] = v;
        augS[n][d]  = v;
    }
    if (wid < 8) {   // agg read + zero: warp wid owns row wid
        float* src = g_agg + (size_t)(base_row + wid)*Hc + lane*8;
        float4 v0 = *(float4*)src, v1 = *(float4*)(src + 4);
        *(float4*)(&augS[wid][4 + lane*8])     = v0;
        *(float4*)(&augS[wid][4 + lane*8 + 4]) = v1;
        float4 z = make_float4(0.f, 0.f, 0.f, 0.f);
        *(float4*)src = z; *(float4*)(src + 4) = z;
    }
    __syncthreads();

    // Layer 1 partials: jh=0 covers groups [0,33), jh=1 covers [33,65)
    {
        float acc[8];
        #pragma unroll
        for (int r = 0; r < 8; r++) acc[r] = 0.f;
        int g0 = jh ? 33 : 0;
        int g1 = jh ? 65 : 33;
        const float* Wb = g_Wo1B + c*4;
        #pragma unroll 8
        for (int g = g0; g < g1; g++) {
            float4 w = *(const float4*)(Wb + g*1024);
            int j0 = g*4;
            #pragma unroll
            for (int r = 0; r < 8; r++) {
                float4 av = *(const float4*)(&augS[r][j0]);
                acc[r] += av.x*w.x + av.y*w.y + av.z*w.z + av.w*w.w;
            }
        }
        #pragma unroll
        for (int r = 0; r < 8; r++) pbS[jh*8 + r][c] = acc[r];
    }
    __syncthreads();
    if (tid < 256) {
        float bb = bo1[c];
        #pragma unroll
        for (int r = 0; r < 8; r++)
            h1S[r][c] = fmaxf(pbS[r][c] + pbS[8 + r][c] + bb, 0.f);
    }
    __syncthreads();

    // Layer 2 partials: jh covers 32 of 64 groups
    {
        float acc[8];
        #pragma unroll
        for (int r = 0; r < 8; r++) acc[r] = 0.f;
        int g0 = jh * 32;
        const float* Wb = g_Wo2B + c*4;
        #pragma unroll 8
        for (int g = g0; g < g0 + 32; g++) {
            float4 w = *(const float4*)(Wb + g*1024);
            int j0 = g*4;
            #pragma unroll
            for (int r = 0; r < 8; r++) {
                float4 av = *(const float4*)(&h1S[r][j0]);
                acc[r] += av.x*w.x + av.y*w.y + av.z*w.z + av.w*w.w;
            }
        }
        #pragma unroll
        for (int r = 0; r < 8; r++) pbS[jh*8 + r][c] = acc[r];
    }
    __syncthreads();
    if (tid < 256) {
        float bb = bo2[c];
        #pragma unroll
        for (int r = 0; r < 8; r++)
            augS[r][4 + c] = fmaxf(pbS[r][c] + pbS[8 + r][c] + bb, 0.f);
    }
    __syncthreads();

    // Layer 3 (256->4) + residual + writes
    if (tid < 32) {
        int n = tid >> 2, d = tid & 3;
        float v = bo3[d];
        #pragma unroll 8
        for (int cc = 0; cc < Hc; cc++) v += augS[n][4 + cc] * wo3S[cc*Dc + d];
        float nl = lastS[n][d] + v;
        int grow = base_row + n;
        g_last[grow*Dc + d] = nl;
        int bt = grow >> 5, gn = grow & 31;
        int b = bt >> 3, tg = bt & 7;
        int t = tg*Pc + step;
        if (t < Tc - 1)
            out[((b*Nc + gn)*(Tc-1) + t)*Dc + d] = nl;
    }
}

// ---------------------------------------------------------------------------
extern "C" void kernel_launch(void* const* d_in, const int* in_sizes, int n_in,
                              void* d_out, int out_size)
{
    const float* inputs    = (const float*)d_in[0];
    const float* rel_graph = (const float*)d_in[1];
    const float* W1  = (const float*)d_in[2];
    const float* b1  = (const float*)d_in[3];
    const float* W2  = (const float*)d_in[4];
    const float* b2  = (const float*)d_in[5];
    const float* Wo1 = (const float*)d_in[6];
    const float* bo1 = (const float*)d_in[7];
    const float* Wo2 = (const float*)d_in[8];
    const float* bo2 = (const float*)d_in[9];
    const float* Wo3 = (const float*)d_in[10];
    const float* bo3 = (const float*)d_in[11];
    const float* gumbel = (const float*)d_in[14];
    float* out = (float*)d_out;

    cudaFuncSetAttribute(k_edge, cudaFuncAttributeMaxDynamicSharedMemorySize, SMEM_TOTAL);

    k_setup<<<128, 256>>>(rel_graph, gumbel, inputs, out);
    k_prep<<<64, 256>>>(W2, W1, Wo1, Wo2);
    for (int p = 0; p < Pc; p++) {
        k_edge<<<ROWS_E/128, 256, SMEM_TOTAL>>>(b1, b2, out, p);
        k_node<<<256, 512>>>(bo1, bo2, Wo3, bo3, out, p);
    }
}

// round 14
// speedup vs baseline: 1.0463x; 1.0208x over previous
#include <cuda_runtime.h>
#include <cuda_fp16.h>
#include <stdint.h>
#include <math.h>

// Problem constants
#define Bc 8
#define Nc 32
#define Tc 32
#define Dc 4
#define Kc 2
#define Hc 256
#define Pc 4
#define Ec 992            // N*(N-1) = 32*31
#define TGc 8             // T/P
#define BTc 64            // B*TG
#define ROWS_E (BTc*Ec)   // 63488 = 2048*31

// Output layout (float32)
#define SZ_PRED (Bc*Nc*(Tc-1)*Dc)
#define OFF_REL SZ_PRED
#define SZ_REL (Bc*Ec*Kc)
#define OFF_HOOK (OFF_REL + SZ_REL)

// Device scratch (no allocation; BSS zero-initialized)
__device__ float g_edges[Ec*Kc];
__device__ float g_last[BTc*Nc*Dc];
__device__ float g_agg[2048*Hc];        // 2 MB; invariant: zero at kernel_launch entry
__device__ uint4 g_W2h[16384];          // W2^T fp16 [e][n][k] swizzled 512B rows (256 KB)
__device__ uint4 g_W1h[512];            // W1^T fp16 [e][n][d] 16B rows (8 KB)
__device__ uint4 g_Wo1h4[17*256*2];     // Wo1 fp16 chunk-major [q][n][16k] (139 KB)
__device__ uint4 g_Wo2h4[16*256*2];     // Wo2 fp16 chunk-major [q][n][16k] (131 KB)

// ---------------------------------------------------------------------------
// smem layout for k_edge (110 KB -> 2 CTAs/SM)
#define SM_A    0            // A fp16 one expert: 128 x 512B = 65536
#define SM_B    65536        // B fp16 n-quarter: 64 x 512B = 32768
#define SM_W1H  98304        // W1h fp16 both experts: 8192
#define SM_PMH  106496       // premsg fp16 128 x 16B = 2048
#define SM_B1   108544       // b1 fp32 both: 2048
#define SM_B2   110592       // b2 fp32 both: 2048
#define SMEM_TOTAL 112640

// smem layout for k_node (dynamic, ~64 KB)
#define NA_A    0            // aug fp16: 16 rows x 560B = 8960
#define NA_H    8960         // h1 fp16: 16 rows x 560B = 8960
#define NA_B    17920        // B chunk double buf: 2 x (256 rows x 48B) = 24576
#define NA_AUG2 42496        // h2 fp32: 16 x 264 = 16896
#define NA_LAST 59392        // 16 x 4 f32 = 256
#define NA_WO3  59648        // 1024 f32 = 4096
#define NA_BO   63744        // bo1 256f + bo2 256f = 2048
#define NSM_TOTAL 65792

static __device__ __forceinline__ uint32_t smem_u32(const void* p) {
    uint32_t a;
    asm("{ .reg .u64 t; cvta.to.shared.u64 t, %1; cvt.u32.u64 %0, t; }" : "=r"(a) : "l"(p));
    return a;
}
#define LDMX4(r0,r1,r2,r3,addr) \
    asm volatile("ldmatrix.sync.aligned.m8n8.x4.shared.b16 {%0,%1,%2,%3}, [%4];" \
        : "=r"(r0), "=r"(r1), "=r"(r2), "=r"(r3) : "r"(addr))
#define LDMX2(r0,r1,addr) \
    asm volatile("ldmatrix.sync.aligned.m8n8.x2.shared.b16 {%0,%1}, [%2];" \
        : "=r"(r0), "=r"(r1) : "r"(addr))
#define MMA16816(c,a0,a1,a2,a3,b0,b1) \
    asm volatile("mma.sync.aligned.m16n8k16.row.col.f32.f16.f16.f32 " \
        "{%0,%1,%2,%3}, {%4,%5,%6,%7}, {%8,%9}, {%0,%1,%2,%3};" \
        : "+f"((c)[0]), "+f"((c)[1]), "+f"((c)[2]), "+f"((c)[3]) \
        : "r"(a0), "r"(a1), "r"(a2), "r"(a3), "r"(b0), "r"(b1))
#define MMA16808(c,a0,a1,b0) \
    asm volatile("mma.sync.aligned.m16n8k8.row.col.f32.f16.f16.f32 " \
        "{%0,%1,%2,%3}, {%4,%5}, {%6}, {%0,%1,%2,%3};" \
        : "+f"((c)[0]), "+f"((c)[1]), "+f"((c)[2]), "+f"((c)[3]) \
        : "r"(a0), "r"(a1), "r"(b0))
#define CP16(dst, src) \
    asm volatile("cp.async.cg.shared.global [%0], [%1], 16;" :: "r"(dst), "l"(src) : "memory")
#define CP_COMMIT() asm volatile("cp.async.commit_group;" ::: "memory")
#define CP_WAIT(n)  asm volatile("cp.async.wait_group %0;" :: "n"(n) : "memory")

static __device__ __forceinline__ int swb(int r, int c) {
    return r*512 + (((c >> 3) ^ (r & 7)) << 4) + (c & 7)*2;
}
static __device__ __forceinline__ int sw_off(int row, int kchunk) {
    return row*512 + ((kchunk ^ (row & 7)) << 4);
}

// Edge GEMM pass: m32n32 per warp over M128 x N64(quarter) x K256
static __device__ __forceinline__ void gemm_q(
    float (&acc)[2][4][4],
    uint32_t aBase, uint32_t bBase,
    const uint32_t (&aRow)[2], const uint32_t (&bRow)[2],
    uint32_t aSel, uint32_t bSel)
{
    #pragma unroll
    for (int mi = 0; mi < 2; mi++)
        #pragma unroll
        for (int nj = 0; nj < 4; nj++)
            #pragma unroll
            for (int c = 0; c < 4; c++) acc[mi][nj][c] = 0.f;

    #pragma unroll 4
    for (int kc = 0; kc < 16; kc++) {
        uint32_t af[2][4], bf[2][4];
        #pragma unroll
        for (int mi = 0; mi < 2; mi++) {
            uint32_t chunk = kc*2 + aSel;
            LDMX4(af[mi][0], af[mi][1], af[mi][2], af[mi][3],
                  aBase + (aRow[mi] ^ (chunk << 4)));
        }
        #pragma unroll
        for (int njp = 0; njp < 2; njp++) {
            uint32_t chunk = kc*2 + bSel;
            LDMX4(bf[njp][0], bf[njp][1], bf[njp][2], bf[njp][3],
                  bBase + (bRow[njp] ^ (chunk << 4)));
        }
        #pragma unroll
        for (int mi = 0; mi < 2; mi++)
            #pragma unroll
            for (int njp = 0; njp < 2; njp++) {
                MMA16816(acc[mi][njp*2],   af[mi][0], af[mi][1], af[mi][2], af[mi][3],
                         bf[njp][0], bf[njp][1]);
                MMA16816(acc[mi][njp*2+1], af[mi][0], af[mi][1], af[mi][2], af[mi][3],
                         bf[njp][2], bf[njp][3]);
            }
    }
}

// ---------------------------------------------------------------------------
__global__ void k_setup(const float* __restrict__ rel_graph,
                        const float* __restrict__ gumbel,
                        const float* __restrict__ inputs,
                        float* __restrict__ out)
{
    int i = blockIdx.x * blockDim.x + threadIdx.x;
    int stride = gridDim.x * blockDim.x;
    if (i < Ec) {
        float l0 = (rel_graph[2*i]   + gumbel[2*i])   * 2.0f;
        float l1 = (rel_graph[2*i+1] + gumbel[2*i+1]) * 2.0f;
        float m  = fmaxf(l0, l1);
        float e0 = expf(l0 - m), e1 = expf(l1 - m);
        float inv = 1.0f / (e0 + e1);
        g_edges[2*i]   = e0 * inv;
        g_edges[2*i+1] = e1 * inv;
    }
    for (int j = i; j < Bc*Ec*Kc; j += stride)
        out[OFF_REL + j] = rel_graph[j % (Ec*Kc)];
    for (int j = i; j < BTc*Nc*Dc; j += stride) {
        int d  = j & 3;
        int n  = (j >> 2) & 31;
        int bt = j >> 7;
        int b  = bt >> 3, tg = bt & 7;
        g_last[j] = inputs[((b*Nc + n)*Tc + tg*Pc)*Dc + d];
    }
    for (int j = i; j < 2048*Hc; j += stride) g_agg[j] = 0.f;
}

// ---------------------------------------------------------------------------
__global__ void k_prep(const float* __restrict__ W2, const float* __restrict__ W1,
                       const float* __restrict__ Wo1, const float* __restrict__ Wo2)
{
    int g = blockIdx.x * blockDim.x + threadIdx.x;
    if (g < 16384) {
        int ex  = g >> 13;
        int rem = g & 8191;
        int n   = rem >> 5;
        int kg  = (rem & 31) * 8;
        float w[8];
        #pragma unroll
        for (int j = 0; j < 8; j++) w[j] = W2[ex*65536 + (kg + j)*256 + n];
        uint4 pk;
        __half2 h0 = __floats2half2_rn(w[0], w[1]);
        __half2 h1 = __floats2half2_rn(w[2], w[3]);
        __half2 h2 = __floats2half2_rn(w[4], w[5]);
        __half2 h3 = __floats2half2_rn(w[6], w[7]);
        pk.x = *(uint32_t*)&h0; pk.y = *(uint32_t*)&h1;
        pk.z = *(uint32_t*)&h2; pk.w = *(uint32_t*)&h3;
        *(uint4*)((char*)g_W2h + ex*131072 + sw_off(n, kg >> 3)) = pk;
    }
    if (g < 512) {
        int ex = g >> 8, n = g & 255;
        float w[8];
        #pragma unroll
        for (int d = 0; d < 8; d++) w[d] = W1[ex*2048 + d*256 + n];
        uint4 pk;
        __half2 h0 = __floats2half2_rn(w[0], w[1]);
        __half2 h1 = __floats2half2_rn(w[2], w[3]);
        __half2 h2 = __floats2half2_rn(w[4], w[5]);
        __half2 h3 = __floats2half2_rn(w[6], w[7]);
        pk.x = *(uint32_t*)&h0; pk.y = *(uint32_t*)&h1;
        pk.z = *(uint32_t*)&h2; pk.w = *(uint32_t*)&h3;
        g_W1h[g] = pk;
    }
    // Node weights fp16 chunk-major: [q][n][16 halves]
    if (g < 17*256) {
        int q = g >> 8, n = g & 255;
        float v[16];
        #pragma unroll
        for (int kk = 0; kk < 16; kk++) {
            int j = q*16 + kk;
            v[kk] = (j < 260) ? Wo1[j*Hc + n] : 0.f;
        }
        __half2 hh[8];
        #pragma unroll
        for (int p = 0; p < 8; p++) hh[p] = __floats2half2_rn(v[2*p], v[2*p+1]);
        uint4 u0, u1;
        u0.x = *(uint32_t*)&hh[0]; u0.y = *(uint32_t*)&hh[1];
        u0.z = *(uint32_t*)&hh[2]; u0.w = *(uint32_t*)&hh[3];
        u1.x = *(uint32_t*)&hh[4]; u1.y = *(uint32_t*)&hh[5];
        u1.z = *(uint32_t*)&hh[6]; u1.w = *(uint32_t*)&hh[7];
        g_Wo1h4[g*2]     = u0;
        g_Wo1h4[g*2 + 1] = u1;
    }
    if (g < 16*256) {
        int q = g >> 8, n = g & 255;
        float v[16];
        #pragma unroll
        for (int kk = 0; kk < 16; kk++)
            v[kk] = Wo2[(q*16 + kk)*Hc + n];
        __half2 hh[8];
        #pragma unroll
        for (int p = 0; p < 8; p++) hh[p] = __floats2half2_rn(v[2*p], v[2*p+1]);
        uint4 u0, u1;
        u0.x = *(uint32_t*)&hh[0]; u0.y = *(uint32_t*)&hh[1];
        u0.z = *(uint32_t*)&hh[2]; u0.w = *(uint32_t*)&hh[3];
        u1.x = *(uint32_t*)&hh[4]; u1.y = *(uint32_t*)&hh[5];
        u1.z = *(uint32_t*)&hh[6]; u1.w = *(uint32_t*)&hh[7];
        g_Wo2h4[g*2]     = u0;
        g_Wo2h4[g*2 + 1] = u1;
    }
}

// ---------------------------------------------------------------------------
// Edge MLP (unchanged, banked at R13)
// ---------------------------------------------------------------------------
__global__ void __launch_bounds__(256, 2) k_edge(
    const float* __restrict__ b1, const float* __restrict__ b2,
    float* __restrict__ out, int step)
{
    extern __shared__ __align__(1024) char sm[];
    uint32_t sb = smem_u32(sm);
    int tid = threadIdx.x, wid = tid >> 5, lane = tid & 31;
    int mbase = blockIdx.x * 128;

    CP16(sb + SM_W1H + tid*16, (const void*)(g_W1h + tid));
    CP16(sb + SM_W1H + 4096 + tid*16, (const void*)(g_W1h + 256 + tid));
    CP_COMMIT();
    {
        const uint4* src = g_W2h;
        uint32_t dst = sb + SM_B + tid*16;
        #pragma unroll
        for (int i = 0; i < 8; i++) CP16(dst + i*4096, (const void*)(src + tid + i*256));
    }
    CP_COMMIT();

    {
        float* d1 = (float*)(sm + SM_B1);
        float* d2 = (float*)(sm + SM_B2);
        d1[tid] = b1[tid]; d1[tid+256] = b1[tid+256];
        d2[tid] = b2[tid]; d2[tid+256] = b2[tid+256];
    }
    if (tid < 128) {
        int grow = mbase + tid;
        int bt = grow / Ec, e = grow - bt*Ec;
        int r  = e / (Nc-1), j = e - r*(Nc-1);
        int s  = j + (j >= r);
        float4 a = *(const float4*)(g_last + (bt*Nc + s)*Dc);
        float4 b = *(const float4*)(g_last + (bt*Nc + r)*Dc);
        uint4 pk;
        __half2 h0 = __floats2half2_rn(a.x, a.y);
        __half2 h1 = __floats2half2_rn(a.z, a.w);
        __half2 h2 = __floats2half2_rn(b.x, b.y);
        __half2 h3 = __floats2half2_rn(b.z, b.w);
        pk.x = *(uint32_t*)&h0; pk.y = *(uint32_t*)&h1;
        pk.z = *(uint32_t*)&h2; pk.w = *(uint32_t*)&h3;
        *(uint4*)(sm + SM_PMH + tid*16) = pk;
    }

    CP_WAIT(1);
    __syncthreads();

    int wm = wid & 3, wn = wid >> 2;
    int lrow = lane >> 2, lane4 = lane & 3;

    uint32_t aRow[2], bRow[2];
    #pragma unroll
    for (int mi = 0; mi < 2; mi++) {
        int row = wm*32 + mi*16 + (lane & 15);
        aRow[mi] = row*512 + ((row & 7) << 4);
    }
    #pragma unroll
    for (int njp = 0; njp < 2; njp++) {
        int row = wn*32 + njp*16 + ((lane >> 4) << 3) + (lane & 7);
        bRow[njp] = row*512 + ((row & 7) << 4);
    }
    uint32_t aSel = lane >> 4, bSel = (lane >> 3) & 1;

    float e0v[4], e1v[4]; int hookr[4];
    #pragma unroll
    for (int qq = 0; qq < 4; qq++) {
        int mi = qq >> 1, rg = qq & 1;
        int grow = mbase + wm*32 + mi*16 + rg*8 + lrow;
        int bt = grow / Ec, eG = grow - bt*Ec;
        e0v[qq] = g_edges[2*eG];
        e1v[qq] = g_edges[2*eG+1];
        int bb = bt >> 3, tg = bt & 7;
        hookr[qq] = ((step*TGc + tg)*Bc + bb)*Ec + eG;
    }
    int gs   = mbase + wm*32;
    int G0   = gs / 31;
    int bnd  = 31 - (gs - G0*31);

    const float* b2s = (const float*)(sm + SM_B2);

    #pragma unroll
    for (int e = 0; e < 2; e++) {
        {
            int m0 = wid * 16;
            uint32_t a0, a1;
            LDMX2(a0, a1, sb + SM_PMH + (m0 + (lane & 15))*16);
            const float* b1e = (const float*)(sm + SM_B1) + e*256;
            #pragma unroll
            for (int nc = 0; nc < 8; nc++) {
                uint32_t bf[4];
                LDMX4(bf[0], bf[1], bf[2], bf[3],
                      sb + SM_W1H + e*4096 + (nc*32 + lane)*16);
                #pragma unroll
                for (int c = 0; c < 4; c++) {
                    float acc[4] = {0.f, 0.f, 0.f, 0.f};
                    MMA16808(acc, a0, a1, bf[c]);
                    int col = nc*32 + c*8 + (lane & 3)*2;
                    float bx = b1e[col], by = b1e[col+1];
                    __half2 v0 = __floats2half2_rn(fmaxf(acc[0]+bx, 0.f), fmaxf(acc[1]+by, 0.f));
                    __half2 v1 = __floats2half2_rn(fmaxf(acc[2]+bx, 0.f), fmaxf(acc[3]+by, 0.f));
                    int r0 = m0 + (lane >> 2), r1 = r0 + 8;
                    *(__half2*)(sm + SM_A + swb(r0, col)) = v0;
                    *(__half2*)(sm + SM_A + swb(r1, col)) = v1;
                }
            }
        }
        CP_WAIT(0);
        __syncthreads();

        #pragma unroll
        for (int q = 0; q < 4; q++) {
            float acc[2][4][4];
            gemm_q(acc, sb + SM_A, sb + SM_B, aRow, bRow, aSel, bSel);
            __syncthreads();

            if (q < 3 || e == 0) {
                int ne = (q < 3) ? e : 1;
                int nq = (q < 3) ? q + 1 : 0;
                const uint4* src = g_W2h + ne*8192 + nq*2048;
                uint32_t dst = sb + SM_B + tid*16;
                #pragma unroll
                for (int i = 0; i < 8; i++) CP16(dst + i*4096, (const void*)(src + tid + i*256));
            }
            CP_COMMIT();

            #pragma unroll
            for (int nj = 0; nj < 4; nj++) {
                int cg = q*64 + wn*32 + nj*8 + lane4*2;
                float bx = b2s[e*256 + cg], by = b2s[e*256 + cg + 1];
                float pA0 = 0.f, pA1 = 0.f, pB0 = 0.f, pB1 = 0.f;
                #pragma unroll
                for (int mi = 0; mi < 2; mi++)
                    #pragma unroll
                    for (int rg = 0; rg < 2; rg++) {
                        int ridx = mi*2 + rg;
                        float sc = e ? e1v[ridx] : e0v[ridx];
                        float v0 = fmaxf(acc[mi][nj][rg*2]   + bx, 0.f) * sc;
                        float v1 = fmaxf(acc[mi][nj][rg*2+1] + by, 0.f) * sc;
                        if (e == 1)
                            *(float2*)(out + OFF_HOOK + (size_t)hookr[ridx]*Hc + cg) =
                                make_float2(v0, v1);
                        int rel = mi*16 + rg*8 + lrow;
                        if (rel < bnd) { pA0 += v0; pA1 += v1; }
                        else           { pB0 += v0; pB1 += v1; }
                    }
                #pragma unroll
                for (int d = 4; d <= 16; d <<= 1) {
                    pA0 += __shfl_xor_sync(0xffffffffu, pA0, d);
                    pA1 += __shfl_xor_sync(0xffffffffu, pA1, d);
                    pB0 += __shfl_xor_sync(0xffffffffu, pB0, d);
                    pB1 += __shfl_xor_sync(0xffffffffu, pB1, d);
                }
                if (lane < 4) {
                    atomicAdd(g_agg + (size_t)G0*Hc + cg,         pA0);
                    atomicAdd(g_agg + (size_t)G0*Hc + cg + 1,     pA1);
                    atomicAdd(g_agg + (size_t)(G0+1)*Hc + cg,     pB0);
                    atomicAdd(g_agg + (size_t)(G0+1)*Hc + cg + 1, pB1);
                }
            }
            CP_WAIT(0);
            __syncthreads();
        }
    }
}

// ---------------------------------------------------------------------------
// Node MLP v6 (HMMA): 128 blocks x 256 threads x 16 rows. Layers 1-2 via
// mma.m16n8k16 fp16 (fp32 accum); weights streamed as fp16 k-chunks (cp.async
// double buffer, 33-chunk stream). Layer 3 + residual fp32.
// ---------------------------------------------------------------------------
static __device__ __forceinline__ void nprefetch(int q, uint32_t dstB, int tid) {
    const char* src = (q < 17)
        ? ((const char*)g_Wo1h4 + q*8192)
        : ((const char*)g_Wo2h4 + (q-17)*8192);
    uint32_t dst = dstB + tid*48;
    const char* s = src + tid*32;
    CP16(dst, s);
    CP16(dst + 16, s + 16);
}

static __device__ __forceinline__ void node_chunk(
    float (&acc)[4][4], uint32_t aBase, int q, uint32_t bBase, int lane, int wn)
{
    uint32_t a0, a1, a2, a3;
    LDMX4(a0, a1, a2, a3, aBase + (lane & 15)*560 + q*32 + (lane >> 4)*16);
    #pragma unroll
    for (int njp = 0; njp < 2; njp++) {
        uint32_t row = wn + njp*16 + ((lane >> 4) << 3) + (lane & 7);
        uint32_t b0, b1, b2, b3;
        LDMX4(b0, b1, b2, b3, bBase + row*48 + ((lane >> 3) & 1)*16);
        MMA16816(acc[njp*2],   a0, a1, a2, a3, b0, b1);
        MMA16816(acc[njp*2+1], a0, a1, a2, a3, b2, b3);
    }
}

__global__ void __launch_bounds__(256) k_node(
    const float* __restrict__ bo1, const float* __restrict__ bo2,
    const float* __restrict__ Wo3, const float* __restrict__ bo3,
    float* __restrict__ out, int step)
{
    extern __shared__ __align__(16) char nsm[];
    uint32_t sb = smem_u32(nsm);
    float* aug2S = (float*)(nsm + NA_AUG2);
    float* lastS = (float*)(nsm + NA_LAST);
    float* wo3S  = (float*)(nsm + NA_WO3);
    float* bo1S  = (float*)(nsm + NA_BO);
    float* bo2S  = (float*)(nsm + NA_BO + 1024);

    int tid = threadIdx.x, wid = tid >> 5, lane = tid & 31;
    int base_row = blockIdx.x * 16;
    int wn = wid * 32;               // warp's n-offset (output cols)

    // prefetch weight chunk 0
    nprefetch(0, sb + NA_B, tid);
    CP_COMMIT();

    // biases + wo3
    bo1S[tid] = bo1[tid];
    bo2S[tid] = bo2[tid];
    #pragma unroll
    for (int i = 0; i < 4; i++) wo3S[tid + i*256] = Wo3[tid + i*256];

    // aug -> fp16 A tile; zero g_agg; last
    #pragma unroll
    for (int rr = 0; rr < 2; rr++) {
        int row = wid*2 + rr;
        float* src = g_agg + (size_t)(base_row + row)*Hc + lane*8;
        float4 v0 = *(float4*)src, v1 = *(float4*)(src + 4);
        __half2 h0 = __floats2half2_rn(v0.x, v0.y);
        __half2 h1 = __floats2half2_rn(v0.z, v0.w);
        __half2 h2 = __floats2half2_rn(v1.x, v1.y);
        __half2 h3 = __floats2half2_rn(v1.z, v1.w);
        uint2 w0, w1;
        w0.x = *(uint32_t*)&h0; w0.y = *(uint32_t*)&h1;
        w1.x = *(uint32_t*)&h2; w1.y = *(uint32_t*)&h3;
        char* dst = nsm + NA_A + row*560 + 8 + lane*16;
        *(uint2*)dst = w0;
        *(uint2*)(dst + 8) = w1;
        float4 z = make_float4(0.f, 0.f, 0.f, 0.f);
        *(float4*)src = z; *(float4*)(src + 4) = z;
    }
    if (tid < 64) {
        int r = tid >> 2, d = tid & 3;
        float v = g_last[(base_row + r)*Dc + d];
        lastS[r*4 + d] = v;
        *(__half*)(nsm + NA_A + r*560 + d*2) = __float2half(v);
    }
    if (tid < 16) {   // zero K pad [260,272)
        char* p = nsm + NA_A + tid*560 + 520;
        *(uint2*)p = make_uint2(0u, 0u);
        *(uint2*)(p + 8) = make_uint2(0u, 0u);
        *(uint2*)(p + 16) = make_uint2(0u, 0u);
    }

    // ---- layer 1: 17 chunks ----
    float acc[4][4];
    #pragma unroll
    for (int t = 0; t < 4; t++)
        #pragma unroll
        for (int c = 0; c < 4; c++) acc[t][c] = 0.f;

    for (int q = 0; q < 17; q++) {
        CP_WAIT(0);
        __syncthreads();
        nprefetch(q + 1, sb + NA_B + ((q+1)&1)*12288, tid);
        CP_COMMIT();
        node_chunk(acc, sb + NA_A, q, sb + NA_B + (q&1)*12288, lane, wn);
    }
    // epilogue 1: bias+relu -> H fp16
    {
        int r0 = lane >> 2, r1 = r0 + 8;
        #pragma unroll
        for (int t = 0; t < 4; t++) {
            int c = wn + t*8 + (lane & 3)*2;
            float bx = bo1S[c], by = bo1S[c+1];
            __half2 p0 = __floats2half2_rn(fmaxf(acc[t][0]+bx, 0.f), fmaxf(acc[t][1]+by, 0.f));
            __half2 p1 = __floats2half2_rn(fmaxf(acc[t][2]+bx, 0.f), fmaxf(acc[t][3]+by, 0.f));
            *(__half2*)(nsm + NA_H + r0*560 + c*2) = p0;
            *(__half2*)(nsm + NA_H + r1*560 + c*2) = p1;
        }
    }
    __syncthreads();

    // ---- layer 2: 16 chunks (stream positions 17..32) ----
    #pragma unroll
    for (int t = 0; t < 4; t++)
        #pragma unroll
        for (int c = 0; c < 4; c++) acc[t][c] = 0.f;

    for (int q2 = 0; q2 < 16; q2++) {
        int q = 17 + q2;
        CP_WAIT(0);
        __syncthreads();
        if (q + 1 < 33) {
            nprefetch(q + 1, sb + NA_B + ((q+1)&1)*12288, tid);
            CP_COMMIT();
        }
        node_chunk(acc, sb + NA_H, q2, sb + NA_B + (q&1)*12288, lane, wn);
    }
    // epilogue 2: bias+relu -> aug2 fp32
    {
        int r0 = lane >> 2, r1 = r0 + 8;
        #pragma unroll
        for (int t = 0; t < 4; t++) {
            int c = wn + t*8 + (lane & 3)*2;
            float bx = bo2S[c], by = bo2S[c+1];
            aug2S[r0*264 + c]     = fmaxf(acc[t][0] + bx, 0.f);
            aug2S[r0*264 + c + 1] = fmaxf(acc[t][1] + by, 0.f);
            aug2S[r1*264 + c]     = fmaxf(acc[t][2] + bx, 0.f);
            aug2S[r1*264 + c + 1] = fmaxf(acc[t][3] + by, 0.f);
        }
    }
    __syncthreads();

    // ---- layer 3 (256->4) + residual + writes ----
    if (tid < 64) {
        int n = tid >> 2, d = tid & 3;
        float v = bo3[d];
        #pragma unroll 8
        for (int cc = 0; cc < Hc; cc++)
            v += aug2S[n*264 + cc] * wo3S[cc*Dc + d];
        float nl = lastS[n*4 + d] + v;
        int grow = base_row + n;
        g_last[grow*Dc + d] = nl;
        int bt = grow >> 5, gn = grow & 31;
        int b = bt >> 3, tg = bt & 7;
        int t = tg*Pc + step;
        if (t < Tc - 1)
            out[((b*Nc + gn)*(Tc-1) + t)*Dc + d] = nl;
    }
}

// ---------------------------------------------------------------------------
extern "C" void kernel_launch(void* const* d_in, const int* in_sizes, int n_in,
                              void* d_out, int out_size)
{
    const float* inputs    = (const float*)d_in[0];
    const float* rel_graph = (const float*)d_in[1];
    const float* W1  = (const float*)d_in[2];
    const float* b1  = (const float*)d_in[3];
    const float* W2  = (const float*)d_in[4];
    const float* b2  = (const float*)d_in[5];
    const float* Wo1 = (const float*)d_in[6];
    const float* bo1 = (const float*)d_in[7];
    const float* Wo2 = (const float*)d_in[8];
    const float* bo2 = (const float*)d_in[9];
    const float* Wo3 = (const float*)d_in[10];
    const float* bo3 = (const float*)d_in[11];
    const float* gumbel = (const float*)d_in[14];
    float* out = (float*)d_out;

    cudaFuncSetAttribute(k_edge, cudaFuncAttributeMaxDynamicSharedMemorySize, SMEM_TOTAL);
    cudaFuncSetAttribute(k_node, cudaFuncAttributeMaxDynamicSharedMemorySize, NSM_TOTAL);

    k_setup<<<128, 256>>>(rel_graph, gumbel, inputs, out);
    k_prep<<<64, 256>>>(W2, W1, Wo1, Wo2);
    for (int p = 0; p < Pc; p++) {
        k_edge<<<ROWS_E/128, 256, SMEM_TOTAL>>>(b1, b2, out, p);
        k_node<<<128, 256, NSM_TOTAL>>>(bo1, bo2, Wo3, bo3, out, p);
    }
}

// round 15
// speedup vs baseline: 1.1011x; 1.0524x over previous
#include <cuda_runtime.h>
#include <cuda_fp16.h>
#include <stdint.h>
#include <math.h>

// Problem constants
#define Bc 8
#define Nc 32
#define Tc 32
#define Dc 4
#define Kc 2
#define Hc 256
#define Pc 4
#define Ec 992            // N*(N-1) = 32*31
#define TGc 8             // T/P
#define BTc 64            // B*TG
#define ROWS_E (BTc*Ec)   // 63488 = 2048*31

// Output layout (float32)
#define SZ_PRED (Bc*Nc*(Tc-1)*Dc)
#define OFF_REL SZ_PRED
#define SZ_REL (Bc*Ec*Kc)
#define OFF_HOOK (OFF_REL + SZ_REL)

// Device scratch (no allocation; BSS zero-initialized)
__device__ float g_edges[Ec*Kc];
__device__ float g_last[BTc*Nc*Dc];
__device__ float g_agg[2048*Hc];        // 2 MB; invariant: zero at kernel_launch entry
__device__ uint4 g_W2h[16384];          // W2^T fp16 [e][n][k] swizzled 512B rows (256 KB)
__device__ uint4 g_W1h[512];            // W1^T fp16 [e][n][d] 16B rows (8 KB)
__device__ uint4 g_Wo1h4[17*256*2];     // Wo1 fp16 chunk-major [q][n][16k] (139 KB)
__device__ uint4 g_Wo2h4[16*256*2];     // Wo2 fp16 chunk-major [q][n][16k] (131 KB)

// ---------------------------------------------------------------------------
// smem layout for k_edge (110 KB -> 2 CTAs/SM)
#define SM_A    0
#define SM_B    65536
#define SM_W1H  98304
#define SM_PMH  106496
#define SM_B1   108544
#define SM_B2   110592
#define SMEM_TOTAL 112640

// smem layout for k_node (dynamic, ~89 KB; 4-deep weight pipeline)
#define NA_A    0            // aug fp16: 16 rows x 560B = 8960
#define NA_H    8960         // h1 fp16: 16 rows x 560B = 8960
#define NA_B    17920        // B chunk 4-buf: 4 x (256 rows x 48B) = 49152
#define NA_AUG2 67072        // h2 fp32: 16 x 264 = 16896
#define NA_LAST 83968        // 16 x 4 f32 = 256
#define NA_WO3  84224        // 1024 f32 = 4096
#define NA_BO   88320        // bo1 256f + bo2 256f = 2048
#define NSM_TOTAL 90368

static __device__ __forceinline__ uint32_t smem_u32(const void* p) {
    uint32_t a;
    asm("{ .reg .u64 t; cvta.to.shared.u64 t, %1; cvt.u32.u64 %0, t; }" : "=r"(a) : "l"(p));
    return a;
}
#define LDMX4(r0,r1,r2,r3,addr) \
    asm volatile("ldmatrix.sync.aligned.m8n8.x4.shared.b16 {%0,%1,%2,%3}, [%4];" \
        : "=r"(r0), "=r"(r1), "=r"(r2), "=r"(r3) : "r"(addr))
#define LDMX2(r0,r1,addr) \
    asm volatile("ldmatrix.sync.aligned.m8n8.x2.shared.b16 {%0,%1}, [%2];" \
        : "=r"(r0), "=r"(r1) : "r"(addr))
#define MMA16816(c,a0,a1,a2,a3,b0,b1) \
    asm volatile("mma.sync.aligned.m16n8k16.row.col.f32.f16.f16.f32 " \
        "{%0,%1,%2,%3}, {%4,%5,%6,%7}, {%8,%9}, {%0,%1,%2,%3};" \
        : "+f"((c)[0]), "+f"((c)[1]), "+f"((c)[2]), "+f"((c)[3]) \
        : "r"(a0), "r"(a1), "r"(a2), "r"(a3), "r"(b0), "r"(b1))
#define MMA16808(c,a0,a1,b0) \
    asm volatile("mma.sync.aligned.m16n8k8.row.col.f32.f16.f16.f32 " \
        "{%0,%1,%2,%3}, {%4,%5}, {%6}, {%0,%1,%2,%3};" \
        : "+f"((c)[0]), "+f"((c)[1]), "+f"((c)[2]), "+f"((c)[3]) \
        : "r"(a0), "r"(a1), "r"(b0))
#define CP16(dst, src) \
    asm volatile("cp.async.cg.shared.global [%0], [%1], 16;" :: "r"(dst), "l"(src) : "memory")
#define CP_COMMIT() asm volatile("cp.async.commit_group;" ::: "memory")
#define CP_WAIT(n)  asm volatile("cp.async.wait_group %0;" :: "n"(n) : "memory")

static __device__ __forceinline__ int swb(int r, int c) {
    return r*512 + (((c >> 3) ^ (r & 7)) << 4) + (c & 7)*2;
}
static __device__ __forceinline__ int sw_off(int row, int kchunk) {
    return row*512 + ((kchunk ^ (row & 7)) << 4);
}

// Edge GEMM pass: m32n32 per warp over M128 x N64(quarter) x K256
static __device__ __forceinline__ void gemm_q(
    float (&acc)[2][4][4],
    uint32_t aBase, uint32_t bBase,
    const uint32_t (&aRow)[2], const uint32_t (&bRow)[2],
    uint32_t aSel, uint32_t bSel)
{
    #pragma unroll
    for (int mi = 0; mi < 2; mi++)
        #pragma unroll
        for (int nj = 0; nj < 4; nj++)
            #pragma unroll
            for (int c = 0; c < 4; c++) acc[mi][nj][c] = 0.f;

    #pragma unroll 4
    for (int kc = 0; kc < 16; kc++) {
        uint32_t af[2][4], bf[2][4];
        #pragma unroll
        for (int mi = 0; mi < 2; mi++) {
            uint32_t chunk = kc*2 + aSel;
            LDMX4(af[mi][0], af[mi][1], af[mi][2], af[mi][3],
                  aBase + (aRow[mi] ^ (chunk << 4)));
        }
        #pragma unroll
        for (int njp = 0; njp < 2; njp++) {
            uint32_t chunk = kc*2 + bSel;
            LDMX4(bf[njp][0], bf[njp][1], bf[njp][2], bf[njp][3],
                  bBase + (bRow[njp] ^ (chunk << 4)));
        }
        #pragma unroll
        for (int mi = 0; mi < 2; mi++)
            #pragma unroll
            for (int njp = 0; njp < 2; njp++) {
                MMA16816(acc[mi][njp*2],   af[mi][0], af[mi][1], af[mi][2], af[mi][3],
                         bf[njp][0], bf[njp][1]);
                MMA16816(acc[mi][njp*2+1], af[mi][0], af[mi][1], af[mi][2], af[mi][3],
                         bf[njp][2], bf[njp][3]);
            }
    }
}

// ---------------------------------------------------------------------------
__global__ void k_setup(const float* __restrict__ rel_graph,
                        const float* __restrict__ gumbel,
                        const float* __restrict__ inputs,
                        float* __restrict__ out)
{
    int i = blockIdx.x * blockDim.x + threadIdx.x;
    int stride = gridDim.x * blockDim.x;
    if (i < Ec) {
        float l0 = (rel_graph[2*i]   + gumbel[2*i])   * 2.0f;
        float l1 = (rel_graph[2*i+1] + gumbel[2*i+1]) * 2.0f;
        float m  = fmaxf(l0, l1);
        float e0 = expf(l0 - m), e1 = expf(l1 - m);
        float inv = 1.0f / (e0 + e1);
        g_edges[2*i]   = e0 * inv;
        g_edges[2*i+1] = e1 * inv;
    }
    for (int j = i; j < Bc*Ec*Kc; j += stride)
        out[OFF_REL + j] = rel_graph[j % (Ec*Kc)];
    for (int j = i; j < BTc*Nc*Dc; j += stride) {
        int d  = j & 3;
        int n  = (j >> 2) & 31;
        int bt = j >> 7;
        int b  = bt >> 3, tg = bt & 7;
        g_last[j] = inputs[((b*Nc + n)*Tc + tg*Pc)*Dc + d];
    }
    for (int j = i; j < 2048*Hc; j += stride) g_agg[j] = 0.f;
}

// ---------------------------------------------------------------------------
__global__ void k_prep(const float* __restrict__ W2, const float* __restrict__ W1,
                       const float* __restrict__ Wo1, const float* __restrict__ Wo2)
{
    int g = blockIdx.x * blockDim.x + threadIdx.x;
    if (g < 16384) {
        int ex  = g >> 13;
        int rem = g & 8191;
        int n   = rem >> 5;
        int kg  = (rem & 31) * 8;
        float w[8];
        #pragma unroll
        for (int j = 0; j < 8; j++) w[j] = W2[ex*65536 + (kg + j)*256 + n];
        uint4 pk;
        __half2 h0 = __floats2half2_rn(w[0], w[1]);
        __half2 h1 = __floats2half2_rn(w[2], w[3]);
        __half2 h2 = __floats2half2_rn(w[4], w[5]);
        __half2 h3 = __floats2half2_rn(w[6], w[7]);
        pk.x = *(uint32_t*)&h0; pk.y = *(uint32_t*)&h1;
        pk.z = *(uint32_t*)&h2; pk.w = *(uint32_t*)&h3;
        *(uint4*)((char*)g_W2h + ex*131072 + sw_off(n, kg >> 3)) = pk;
    }
    if (g < 512) {
        int ex = g >> 8, n = g & 255;
        float w[8];
        #pragma unroll
        for (int d = 0; d < 8; d++) w[d] = W1[ex*2048 + d*256 + n];
        uint4 pk;
        __half2 h0 = __floats2half2_rn(w[0], w[1]);
        __half2 h1 = __floats2half2_rn(w[2], w[3]);
        __half2 h2 = __floats2half2_rn(w[4], w[5]);
        __half2 h3 = __floats2half2_rn(w[6], w[7]);
        pk.x = *(uint32_t*)&h0; pk.y = *(uint32_t*)&h1;
        pk.z = *(uint32_t*)&h2; pk.w = *(uint32_t*)&h3;
        g_W1h[g] = pk;
    }
    // Node weights fp16 chunk-major: [q][n][16 halves]
    if (g < 17*256) {
        int q = g >> 8, n = g & 255;
        float v[16];
        #pragma unroll
        for (int kk = 0; kk < 16; kk++) {
            int j = q*16 + kk;
            v[kk] = (j < 260) ? Wo1[j*Hc + n] : 0.f;
        }
        __half2 hh[8];
        #pragma unroll
        for (int p = 0; p < 8; p++) hh[p] = __floats2half2_rn(v[2*p], v[2*p+1]);
        uint4 u0, u1;
        u0.x = *(uint32_t*)&hh[0]; u0.y = *(uint32_t*)&hh[1];
        u0.z = *(uint32_t*)&hh[2]; u0.w = *(uint32_t*)&hh[3];
        u1.x = *(uint32_t*)&hh[4]; u1.y = *(uint32_t*)&hh[5];
        u1.z = *(uint32_t*)&hh[6]; u1.w = *(uint32_t*)&hh[7];
        g_Wo1h4[g*2]     = u0;
        g_Wo1h4[g*2 + 1] = u1;
    }
    if (g < 16*256) {
        int q = g >> 8, n = g & 255;
        float v[16];
        #pragma unroll
        for (int kk = 0; kk < 16; kk++)
            v[kk] = Wo2[(q*16 + kk)*Hc + n];
        __half2 hh[8];
        #pragma unroll
        for (int p = 0; p < 8; p++) hh[p] = __floats2half2_rn(v[2*p], v[2*p+1]);
        uint4 u0, u1;
        u0.x = *(uint32_t*)&hh[0]; u0.y = *(uint32_t*)&hh[1];
        u0.z = *(uint32_t*)&hh[2]; u0.w = *(uint32_t*)&hh[3];
        u1.x = *(uint32_t*)&hh[4]; u1.y = *(uint32_t*)&hh[5];
        u1.z = *(uint32_t*)&hh[6]; u1.w = *(uint32_t*)&hh[7];
        g_Wo2h4[g*2]     = u0;
        g_Wo2h4[g*2 + 1] = u1;
    }
}

// ---------------------------------------------------------------------------
// Edge MLP (unchanged, banked)
// ---------------------------------------------------------------------------
__global__ void __launch_bounds__(256, 2) k_edge(
    const float* __restrict__ b1, const float* __restrict__ b2,
    float* __restrict__ out, int step)
{
    extern __shared__ __align__(1024) char sm[];
    uint32_t sb = smem_u32(sm);
    int tid = threadIdx.x, wid = tid >> 5, lane = tid & 31;
    int mbase = blockIdx.x * 128;

    CP16(sb + SM_W1H + tid*16, (const void*)(g_W1h + tid));
    CP16(sb + SM_W1H + 4096 + tid*16, (const void*)(g_W1h + 256 + tid));
    CP_COMMIT();
    {
        const uint4* src = g_W2h;
        uint32_t dst = sb + SM_B + tid*16;
        #pragma unroll
        for (int i = 0; i < 8; i++) CP16(dst + i*4096, (const void*)(src + tid + i*256));
    }
    CP_COMMIT();

    {
        float* d1 = (float*)(sm + SM_B1);
        float* d2 = (float*)(sm + SM_B2);
        d1[tid] = b1[tid]; d1[tid+256] = b1[tid+256];
        d2[tid] = b2[tid]; d2[tid+256] = b2[tid+256];
    }
    if (tid < 128) {
        int grow = mbase + tid;
        int bt = grow / Ec, e = grow - bt*Ec;
        int r  = e / (Nc-1), j = e - r*(Nc-1);
        int s  = j + (j >= r);
        float4 a = *(const float4*)(g_last + (bt*Nc + s)*Dc);
        float4 b = *(const float4*)(g_last + (bt*Nc + r)*Dc);
        uint4 pk;
        __half2 h0 = __floats2half2_rn(a.x, a.y);
        __half2 h1 = __floats2half2_rn(a.z, a.w);
        __half2 h2 = __floats2half2_rn(b.x, b.y);
        __half2 h3 = __floats2half2_rn(b.z, b.w);
        pk.x = *(uint32_t*)&h0; pk.y = *(uint32_t*)&h1;
        pk.z = *(uint32_t*)&h2; pk.w = *(uint32_t*)&h3;
        *(uint4*)(sm + SM_PMH + tid*16) = pk;
    }

    CP_WAIT(1);
    __syncthreads();

    int wm = wid & 3, wn = wid >> 2;
    int lrow = lane >> 2, lane4 = lane & 3;

    uint32_t aRow[2], bRow[2];
    #pragma unroll
    for (int mi = 0; mi < 2; mi++) {
        int row = wm*32 + mi*16 + (lane & 15);
        aRow[mi] = row*512 + ((row & 7) << 4);
    }
    #pragma unroll
    for (int njp = 0; njp < 2; njp++) {
        int row = wn*32 + njp*16 + ((lane >> 4) << 3) + (lane & 7);
        bRow[njp] = row*512 + ((row & 7) << 4);
    }
    uint32_t aSel = lane >> 4, bSel = (lane >> 3) & 1;

    float e0v[4], e1v[4]; int hookr[4];
    #pragma unroll
    for (int qq = 0; qq < 4; qq++) {
        int mi = qq >> 1, rg = qq & 1;
        int grow = mbase + wm*32 + mi*16 + rg*8 + lrow;
        int bt = grow / Ec, eG = grow - bt*Ec;
        e0v[qq] = g_edges[2*eG];
        e1v[qq] = g_edges[2*eG+1];
        int bb = bt >> 3, tg = bt & 7;
        hookr[qq] = ((step*TGc + tg)*Bc + bb)*Ec + eG;
    }
    int gs   = mbase + wm*32;
    int G0   = gs / 31;
    int bnd  = 31 - (gs - G0*31);

    const float* b2s = (const float*)(sm + SM_B2);

    #pragma unroll
    for (int e = 0; e < 2; e++) {
        {
            int m0 = wid * 16;
            uint32_t a0, a1;
            LDMX2(a0, a1, sb + SM_PMH + (m0 + (lane & 15))*16);
            const float* b1e = (const float*)(sm + SM_B1) + e*256;
            #pragma unroll
            for (int nc = 0; nc < 8; nc++) {
                uint32_t bf[4];
                LDMX4(bf[0], bf[1], bf[2], bf[3],
                      sb + SM_W1H + e*4096 + (nc*32 + lane)*16);
                #pragma unroll
                for (int c = 0; c < 4; c++) {
                    float acc[4] = {0.f, 0.f, 0.f, 0.f};
                    MMA16808(acc, a0, a1, bf[c]);
                    int col = nc*32 + c*8 + (lane & 3)*2;
                    float bx = b1e[col], by = b1e[col+1];
                    __half2 v0 = __floats2half2_rn(fmaxf(acc[0]+bx, 0.f), fmaxf(acc[1]+by, 0.f));
                    __half2 v1 = __floats2half2_rn(fmaxf(acc[2]+bx, 0.f), fmaxf(acc[3]+by, 0.f));
                    int r0 = m0 + (lane >> 2), r1 = r0 + 8;
                    *(__half2*)(sm + SM_A + swb(r0, col)) = v0;
                    *(__half2*)(sm + SM_A + swb(r1, col)) = v1;
                }
            }
        }
        CP_WAIT(0);
        __syncthreads();

        #pragma unroll
        for (int q = 0; q < 4; q++) {
            float acc[2][4][4];
            gemm_q(acc, sb + SM_A, sb + SM_B, aRow, bRow, aSel, bSel);
            __syncthreads();

            if (q < 3 || e == 0) {
                int ne = (q < 3) ? e : 1;
                int nq = (q < 3) ? q + 1 : 0;
                const uint4* src = g_W2h + ne*8192 + nq*2048;
                uint32_t dst = sb + SM_B + tid*16;
                #pragma unroll
                for (int i = 0; i < 8; i++) CP16(dst + i*4096, (const void*)(src + tid + i*256));
            }
            CP_COMMIT();

            #pragma unroll
            for (int nj = 0; nj < 4; nj++) {
                int cg = q*64 + wn*32 + nj*8 + lane4*2;
                float bx = b2s[e*256 + cg], by = b2s[e*256 + cg + 1];
                float pA0 = 0.f, pA1 = 0.f, pB0 = 0.f, pB1 = 0.f;
                #pragma unroll
                for (int mi = 0; mi < 2; mi++)
                    #pragma unroll
                    for (int rg = 0; rg < 2; rg++) {
                        int ridx = mi*2 + rg;
                        float sc = e ? e1v[ridx] : e0v[ridx];
                        float v0 = fmaxf(acc[mi][nj][rg*2]   + bx, 0.f) * sc;
                        float v1 = fmaxf(acc[mi][nj][rg*2+1] + by, 0.f) * sc;
                        if (e == 1)
                            *(float2*)(out + OFF_HOOK + (size_t)hookr[ridx]*Hc + cg) =
                                make_float2(v0, v1);
                        int rel = mi*16 + rg*8 + lrow;
                        if (rel < bnd) { pA0 += v0; pA1 += v1; }
                        else           { pB0 += v0; pB1 += v1; }
                    }
                #pragma unroll
                for (int d = 4; d <= 16; d <<= 1) {
                    pA0 += __shfl_xor_sync(0xffffffffu, pA0, d);
                    pA1 += __shfl_xor_sync(0xffffffffu, pA1, d);
                    pB0 += __shfl_xor_sync(0xffffffffu, pB0, d);
                    pB1 += __shfl_xor_sync(0xffffffffu, pB1, d);
                }
                if (lane < 4) {
                    atomicAdd(g_agg + (size_t)G0*Hc + cg,         pA0);
                    atomicAdd(g_agg + (size_t)G0*Hc + cg + 1,     pA1);
                    atomicAdd(g_agg + (size_t)(G0+1)*Hc + cg,     pB0);
                    atomicAdd(g_agg + (size_t)(G0+1)*Hc + cg + 1, pB1);
                }
            }
            CP_WAIT(0);
            __syncthreads();
        }
    }
}

// ---------------------------------------------------------------------------
// Node MLP v7 (HMMA, 4-deep pipelined weight stream)
// ---------------------------------------------------------------------------
static __device__ __forceinline__ void nprefetch(int q, uint32_t dstB, int tid) {
    const char* src = (q < 17)
        ? ((const char*)g_Wo1h4 + q*8192)
        : ((const char*)g_Wo2h4 + (q-17)*8192);
    uint32_t dst = dstB + tid*48;
    const char* s = src + tid*32;
    CP16(dst, s);
    CP16(dst + 16, s + 16);
}

static __device__ __forceinline__ void node_chunk(
    float (&acc)[4][4], uint32_t aBase, int q, uint32_t bBase, int lane, int wn)
{
    uint32_t a0, a1, a2, a3;
    LDMX4(a0, a1, a2, a3, aBase + (lane & 15)*560 + q*32 + (lane >> 4)*16);
    #pragma unroll
    for (int njp = 0; njp < 2; njp++) {
        uint32_t row = wn + njp*16 + ((lane >> 4) << 3) + (lane & 7);
        uint32_t b0, b1, b2, b3;
        LDMX4(b0, b1, b2, b3, bBase + row*48 + ((lane >> 3) & 1)*16);
        MMA16816(acc[njp*2],   a0, a1, a2, a3, b0, b1);
        MMA16816(acc[njp*2+1], a0, a1, a2, a3, b2, b3);
    }
}

__global__ void __launch_bounds__(256) k_node(
    const float* __restrict__ bo1, const float* __restrict__ bo2,
    const float* __restrict__ Wo3, const float* __restrict__ bo3,
    float* __restrict__ out, int step)
{
    extern __shared__ __align__(16) char nsm[];
    uint32_t sb = smem_u32(nsm);
    float* aug2S = (float*)(nsm + NA_AUG2);
    float* lastS = (float*)(nsm + NA_LAST);
    float* wo3S  = (float*)(nsm + NA_WO3);
    float* bo1S  = (float*)(nsm + NA_BO);
    float* bo2S  = (float*)(nsm + NA_BO + 1024);

    int tid = threadIdx.x, wid = tid >> 5, lane = tid & 31;
    int base_row = blockIdx.x * 16;
    int wn = wid * 32;

    // prologue: prefetch chunks 0..2, one commit group each (ordered!)
    nprefetch(0, sb + NA_B, tid);             CP_COMMIT();
    nprefetch(1, sb + NA_B + 12288, tid);     CP_COMMIT();
    nprefetch(2, sb + NA_B + 24576, tid);     CP_COMMIT();

    bo1S[tid] = bo1[tid];
    bo2S[tid] = bo2[tid];
    #pragma unroll
    for (int i = 0; i < 4; i++) wo3S[tid + i*256] = Wo3[tid + i*256];

    // aug -> fp16 A tile; zero g_agg; last
    #pragma unroll
    for (int rr = 0; rr < 2; rr++) {
        int row = wid*2 + rr;
        float* src = g_agg + (size_t)(base_row + row)*Hc + lane*8;
        float4 v0 = *(float4*)src, v1 = *(float4*)(src + 4);
        __half2 h0 = __floats2half2_rn(v0.x, v0.y);
        __half2 h1 = __floats2half2_rn(v0.z, v0.w);
        __half2 h2 = __floats2half2_rn(v1.x, v1.y);
        __half2 h3 = __floats2half2_rn(v1.z, v1.w);
        uint2 w0, w1;
        w0.x = *(uint32_t*)&h0; w0.y = *(uint32_t*)&h1;
        w1.x = *(uint32_t*)&h2; w1.y = *(uint32_t*)&h3;
        char* dst = nsm + NA_A + row*560 + 8 + lane*16;
        *(uint2*)dst = w0;
        *(uint2*)(dst + 8) = w1;
        float4 z = make_float4(0.f, 0.f, 0.f, 0.f);
        *(float4*)src = z; *(float4*)(src + 4) = z;
    }
    if (tid < 64) {
        int r = tid >> 2, d = tid & 3;
        float v = g_last[(base_row + r)*Dc + d];
        lastS[r*4 + d] = v;
        *(__half*)(nsm + NA_A + r*560 + d*2) = __float2half(v);
    }
    if (tid < 16) {   // zero K pad [260,272)
        char* p = nsm + NA_A + tid*560 + 520;
        *(uint2*)p = make_uint2(0u, 0u);
        *(uint2*)(p + 8) = make_uint2(0u, 0u);
        *(uint2*)(p + 16) = make_uint2(0u, 0u);
    }

    // ---- layer 1: chunks 0..16 (depth-3 pipeline; CP_WAIT(2) => chunk q done) ----
    float acc[4][4];
    #pragma unroll
    for (int t = 0; t < 4; t++)
        #pragma unroll
        for (int c = 0; c < 4; c++) acc[t][c] = 0.f;

    for (int q = 0; q < 17; q++) {
        CP_WAIT(2);
        __syncthreads();
        if (q + 3 < 33) nprefetch(q + 3, sb + NA_B + ((q+3)&3)*12288, tid);
        CP_COMMIT();   // empty at the tail; keeps group numbering aligned
        node_chunk(acc, sb + NA_A, q, sb + NA_B + (q&3)*12288, lane, wn);
    }
    // epilogue 1: bias+relu -> H fp16
    {
        int r0 = lane >> 2, r1 = r0 + 8;
        #pragma unroll
        for (int t = 0; t < 4; t++) {
            int c = wn + t*8 + (lane & 3)*2;
            float bx = bo1S[c], by = bo1S[c+1];
            __half2 p0 = __floats2half2_rn(fmaxf(acc[t][0]+bx, 0.f), fmaxf(acc[t][1]+by, 0.f));
            __half2 p1 = __floats2half2_rn(fmaxf(acc[t][2]+bx, 0.f), fmaxf(acc[t][3]+by, 0.f));
            *(__half2*)(nsm + NA_H + r0*560 + c*2) = p0;
            *(__half2*)(nsm + NA_H + r1*560 + c*2) = p1;
        }
    }
    __syncthreads();

    // ---- layer 2: chunks 17..32 ----
    #pragma unroll
    for (int t = 0; t < 4; t++)
        #pragma unroll
        for (int c = 0; c < 4; c++) acc[t][c] = 0.f;

    for (int q2 = 0; q2 < 16; q2++) {
        int q = 17 + q2;
        CP_WAIT(2);
        __syncthreads();
        if (q + 3 < 33) nprefetch(q + 3, sb + NA_B + ((q+3)&3)*12288, tid);
        CP_COMMIT();
        node_chunk(acc, sb + NA_H, q2, sb + NA_B + (q&3)*12288, lane, wn);
    }
    // epilogue 2: bias+relu -> aug2 fp32
    {
        int r0 = lane >> 2, r1 = r0 + 8;
        #pragma unroll
        for (int t = 0; t < 4; t++) {
            int c = wn + t*8 + (lane & 3)*2;
            float bx = bo2S[c], by = bo2S[c+1];
            aug2S[r0*264 + c]     = fmaxf(acc[t][0] + bx, 0.f);
            aug2S[r0*264 + c + 1] = fmaxf(acc[t][1] + by, 0.f);
            aug2S[r1*264 + c]     = fmaxf(acc[t][2] + bx, 0.f);
            aug2S[r1*264 + c + 1] = fmaxf(acc[t][3] + by, 0.f);
        }
    }
    __syncthreads();

    // ---- layer 3 (256->4) + residual + writes ----
    if (tid < 64) {
        int n = tid >> 2, d = tid & 3;
        float v = bo3[d];
        #pragma unroll 8
        for (int cc = 0; cc < Hc; cc++)
            v += aug2S[n*264 + cc] * wo3S[cc*Dc + d];
        float nl = lastS[n*4 + d] + v;
        int grow = base_row + n;
        g_last[grow*Dc + d] = nl;
        int bt = grow >> 5, gn = grow & 31;
        int b = bt >> 3, tg = bt & 7;
        int t = tg*Pc + step;
        if (t < Tc - 1)
            out[((b*Nc + gn)*(Tc-1) + t)*Dc + d] = nl;
    }
}

// ---------------------------------------------------------------------------
extern "C" void kernel_launch(void* const* d_in, const int* in_sizes, int n_in,
                              void* d_out, int out_size)
{
    const float* inputs    = (const float*)d_in[0];
    const float* rel_graph = (const float*)d_in[1];
    const float* W1  = (const float*)d_in[2];
    const float* b1  = (const float*)d_in[3];
    const float* W2  = (const float*)d_in[4];
    const float* b2  = (const float*)d_in[5];
    const float* Wo1 = (const float*)d_in[6];
    const float* bo1 = (const float*)d_in[7];
    const float* Wo2 = (const float*)d_in[8];
    const float* bo2 = (const float*)d_in[9];
    const float* Wo3 = (const float*)d_in[10];
    const float* bo3 = (const float*)d_in[11];
    const float* gumbel = (const float*)d_in[14];
    float* out = (float*)d_out;

    cudaFuncSetAttribute(k_edge, cudaFuncAttributeMaxDynamicSharedMemorySize, SMEM_TOTAL);
    cudaFuncSetAttribute(k_node, cudaFuncAttributeMaxDynamicSharedMemorySize, NSM_TOTAL);

    k_setup<<<128, 256>>>(rel_graph, gumbel, inputs, out);
    k_prep<<<64, 256>>>(W2, W1, Wo1, Wo2);
    for (int p = 0; p < Pc; p++) {
        k_edge<<<ROWS_E/128, 256, SMEM_TOTAL>>>(b1, b2, out, p);
        k_node<<<128, 256, NSM_TOTAL>>>(bo1, bo2, Wo3, bo3, out, p);
    }
}

// round 16
// speedup vs baseline: 1.1426x; 1.0377x over previous
#include <cuda_runtime.h>
#include <cuda_fp16.h>
#include <stdint.h>
#include <math.h>

// Problem constants
#define Bc 8
#define Nc 32
#define Tc 32
#define Dc 4
#define Kc 2
#define Hc 256
#define Pc 4
#define Ec 992            // N*(N-1) = 32*31
#define TGc 8             // T/P
#define BTc 64            // B*TG
#define ROWS_E (BTc*Ec)   // 63488 = 2048*31

// Output layout (float32)
#define SZ_PRED (Bc*Nc*(Tc-1)*Dc)
#define OFF_REL SZ_PRED
#define SZ_REL (Bc*Ec*Kc)
#define OFF_HOOK (OFF_REL + SZ_REL)

// Device scratch (no allocation; BSS zero-initialized)
__device__ float g_edges[Ec*Kc];
__device__ float g_last[BTc*Nc*Dc];
__device__ float g_agg[2048*Hc];        // 2 MB; invariant: zero at kernel_launch entry
__device__ uint4 g_W2h[16384];          // W2^T fp16 [e][n][k] swizzled 512B rows (256 KB)
__device__ uint4 g_W1h[512];            // W1^T fp16 [e][n][d] 16B rows (8 KB)
__device__ uint4 g_Wo1h4[17*256*2];     // Wo1 fp16 chunk-major [q][n][16k] (139 KB)
__device__ uint4 g_Wo2h4[16*256*2];     // Wo2 fp16 chunk-major [q][n][16k] (131 KB)

// ---------------------------------------------------------------------------
// smem layout for k_edge (110 KB -> 2 CTAs/SM)
#define SM_A    0
#define SM_B    65536
#define SM_W1H  98304
#define SM_PMH  106496
#define SM_B1   108544
#define SM_B2   110592
#define SMEM_TOTAL 112640

// smem layout for k_node (dynamic, ~113 KB; 6-buffer / depth-5 weight pipeline)
#define NA_A    0            // aug fp16: 16 rows x 560B = 8960
#define NA_H    8960         // h1 fp16: 16 rows x 560B = 8960
#define NA_B    17920        // B chunk 6-buf: 6 x 12288 = 73728
#define NA_AUG2 91648        // h2 fp32: 16 x 264 = 16896
#define NA_LAST 108544       // 16 x 4 f32 = 256
#define NA_WO3  108800       // 1024 f32 = 4096
#define NA_BO   112896       // bo1 256f + bo2 256f = 2048
#define NSM_TOTAL 114944

static __device__ __forceinline__ uint32_t smem_u32(const void* p) {
    uint32_t a;
    asm("{ .reg .u64 t; cvta.to.shared.u64 t, %1; cvt.u32.u64 %0, t; }" : "=r"(a) : "l"(p));
    return a;
}
#define LDMX4(r0,r1,r2,r3,addr) \
    asm volatile("ldmatrix.sync.aligned.m8n8.x4.shared.b16 {%0,%1,%2,%3}, [%4];" \
        : "=r"(r0), "=r"(r1), "=r"(r2), "=r"(r3) : "r"(addr))
#define LDMX2(r0,r1,addr) \
    asm volatile("ldmatrix.sync.aligned.m8n8.x2.shared.b16 {%0,%1}, [%2];" \
        : "=r"(r0), "=r"(r1) : "r"(addr))
#define MMA16816(c,a0,a1,a2,a3,b0,b1) \
    asm volatile("mma.sync.aligned.m16n8k16.row.col.f32.f16.f16.f32 " \
        "{%0,%1,%2,%3}, {%4,%5,%6,%7}, {%8,%9}, {%0,%1,%2,%3};" \
        : "+f"((c)[0]), "+f"((c)[1]), "+f"((c)[2]), "+f"((c)[3]) \
        : "r"(a0), "r"(a1), "r"(a2), "r"(a3), "r"(b0), "r"(b1))
#define MMA16808(c,a0,a1,b0) \
    asm volatile("mma.sync.aligned.m16n8k8.row.col.f32.f16.f16.f32 " \
        "{%0,%1,%2,%3}, {%4,%5}, {%6}, {%0,%1,%2,%3};" \
        : "+f"((c)[0]), "+f"((c)[1]), "+f"((c)[2]), "+f"((c)[3]) \
        : "r"(a0), "r"(a1), "r"(b0))
#define CP16(dst, src) \
    asm volatile("cp.async.cg.shared.global [%0], [%1], 16;" :: "r"(dst), "l"(src) : "memory")
#define CP_COMMIT() asm volatile("cp.async.commit_group;" ::: "memory")
#define CP_WAIT(n)  asm volatile("cp.async.wait_group %0;" :: "n"(n) : "memory")

static __device__ __forceinline__ int swb(int r, int c) {
    return r*512 + (((c >> 3) ^ (r & 7)) << 4) + (c & 7)*2;
}
static __device__ __forceinline__ int sw_off(int row, int kchunk) {
    return row*512 + ((kchunk ^ (row & 7)) << 4);
}

// Edge GEMM pass: m32n32 per warp over M128 x N64(quarter) x K256
static __device__ __forceinline__ void gemm_q(
    float (&acc)[2][4][4],
    uint32_t aBase, uint32_t bBase,
    const uint32_t (&aRow)[2], const uint32_t (&bRow)[2],
    uint32_t aSel, uint32_t bSel)
{
    #pragma unroll
    for (int mi = 0; mi < 2; mi++)
        #pragma unroll
        for (int nj = 0; nj < 4; nj++)
            #pragma unroll
            for (int c = 0; c < 4; c++) acc[mi][nj][c] = 0.f;

    #pragma unroll 4
    for (int kc = 0; kc < 16; kc++) {
        uint32_t af[2][4], bf[2][4];
        #pragma unroll
        for (int mi = 0; mi < 2; mi++) {
            uint32_t chunk = kc*2 + aSel;
            LDMX4(af[mi][0], af[mi][1], af[mi][2], af[mi][3],
                  aBase + (aRow[mi] ^ (chunk << 4)));
        }
        #pragma unroll
        for (int njp = 0; njp < 2; njp++) {
            uint32_t chunk = kc*2 + bSel;
            LDMX4(bf[njp][0], bf[njp][1], bf[njp][2], bf[njp][3],
                  bBase + (bRow[njp] ^ (chunk << 4)));
        }
        #pragma unroll
        for (int mi = 0; mi < 2; mi++)
            #pragma unroll
            for (int njp = 0; njp < 2; njp++) {
                MMA16816(acc[mi][njp*2],   af[mi][0], af[mi][1], af[mi][2], af[mi][3],
                         bf[njp][0], bf[njp][1]);
                MMA16816(acc[mi][njp*2+1], af[mi][0], af[mi][1], af[mi][2], af[mi][3],
                         bf[njp][2], bf[njp][3]);
            }
    }
}

// ---------------------------------------------------------------------------
__global__ void k_setup(const float* __restrict__ rel_graph,
                        const float* __restrict__ gumbel,
                        const float* __restrict__ inputs,
                        float* __restrict__ out)
{
    int i = blockIdx.x * blockDim.x + threadIdx.x;
    int stride = gridDim.x * blockDim.x;
    if (i < Ec) {
        float l0 = (rel_graph[2*i]   + gumbel[2*i])   * 2.0f;
        float l1 = (rel_graph[2*i+1] + gumbel[2*i+1]) * 2.0f;
        float m  = fmaxf(l0, l1);
        float e0 = expf(l0 - m), e1 = expf(l1 - m);
        float inv = 1.0f / (e0 + e1);
        g_edges[2*i]   = e0 * inv;
        g_edges[2*i+1] = e1 * inv;
    }
    for (int j = i; j < Bc*Ec*Kc; j += stride)
        out[OFF_REL + j] = rel_graph[j % (Ec*Kc)];
    for (int j = i; j < BTc*Nc*Dc; j += stride) {
        int d  = j & 3;
        int n  = (j >> 2) & 31;
        int bt = j >> 7;
        int b  = bt >> 3, tg = bt & 7;
        g_last[j] = inputs[((b*Nc + n)*Tc + tg*Pc)*Dc + d];
    }
    for (int j = i; j < 2048*Hc; j += stride) g_agg[j] = 0.f;
}

// ---------------------------------------------------------------------------
__global__ void k_prep(const float* __restrict__ W2, const float* __restrict__ W1,
                       const float* __restrict__ Wo1, const float* __restrict__ Wo2)
{
    int g = blockIdx.x * blockDim.x + threadIdx.x;
    if (g < 16384) {
        int ex  = g >> 13;
        int rem = g & 8191;
        int n   = rem >> 5;
        int kg  = (rem & 31) * 8;
        float w[8];
        #pragma unroll
        for (int j = 0; j < 8; j++) w[j] = W2[ex*65536 + (kg + j)*256 + n];
        uint4 pk;
        __half2 h0 = __floats2half2_rn(w[0], w[1]);
        __half2 h1 = __floats2half2_rn(w[2], w[3]);
        __half2 h2 = __floats2half2_rn(w[4], w[5]);
        __half2 h3 = __floats2half2_rn(w[6], w[7]);
        pk.x = *(uint32_t*)&h0; pk.y = *(uint32_t*)&h1;
        pk.z = *(uint32_t*)&h2; pk.w = *(uint32_t*)&h3;
        *(uint4*)((char*)g_W2h + ex*131072 + sw_off(n, kg >> 3)) = pk;
    }
    if (g < 512) {
        int ex = g >> 8, n = g & 255;
        float w[8];
        #pragma unroll
        for (int d = 0; d < 8; d++) w[d] = W1[ex*2048 + d*256 + n];
        uint4 pk;
        __half2 h0 = __floats2half2_rn(w[0], w[1]);
        __half2 h1 = __floats2half2_rn(w[2], w[3]);
        __half2 h2 = __floats2half2_rn(w[4], w[5]);
        __half2 h3 = __floats2half2_rn(w[6], w[7]);
        pk.x = *(uint32_t*)&h0; pk.y = *(uint32_t*)&h1;
        pk.z = *(uint32_t*)&h2; pk.w = *(uint32_t*)&h3;
        g_W1h[g] = pk;
    }
    // Node weights fp16 chunk-major: [q][n][16 halves]
    if (g < 17*256) {
        int q = g >> 8, n = g & 255;
        float v[16];
        #pragma unroll
        for (int kk = 0; kk < 16; kk++) {
            int j = q*16 + kk;
            v[kk] = (j < 260) ? Wo1[j*Hc + n] : 0.f;
        }
        __half2 hh[8];
        #pragma unroll
        for (int p = 0; p < 8; p++) hh[p] = __floats2half2_rn(v[2*p], v[2*p+1]);
        uint4 u0, u1;
        u0.x = *(uint32_t*)&hh[0]; u0.y = *(uint32_t*)&hh[1];
        u0.z = *(uint32_t*)&hh[2]; u0.w = *(uint32_t*)&hh[3];
        u1.x = *(uint32_t*)&hh[4]; u1.y = *(uint32_t*)&hh[5];
        u1.z = *(uint32_t*)&hh[6]; u1.w = *(uint32_t*)&hh[7];
        g_Wo1h4[g*2]     = u0;
        g_Wo1h4[g*2 + 1] = u1;
    }
    if (g < 16*256) {
        int q = g >> 8, n = g & 255;
        float v[16];
        #pragma unroll
        for (int kk = 0; kk < 16; kk++)
            v[kk] = Wo2[(q*16 + kk)*Hc + n];
        __half2 hh[8];
        #pragma unroll
        for (int p = 0; p < 8; p++) hh[p] = __floats2half2_rn(v[2*p], v[2*p+1]);
        uint4 u0, u1;
        u0.x = *(uint32_t*)&hh[0]; u0.y = *(uint32_t*)&hh[1];
        u0.z = *(uint32_t*)&hh[2]; u0.w = *(uint32_t*)&hh[3];
        u1.x = *(uint32_t*)&hh[4]; u1.y = *(uint32_t*)&hh[5];
        u1.z = *(uint32_t*)&hh[6]; u1.w = *(uint32_t*)&hh[7];
        g_Wo2h4[g*2]     = u0;
        g_Wo2h4[g*2 + 1] = u1;
    }
}

// ---------------------------------------------------------------------------
// Edge MLP (unchanged, banked)
// ---------------------------------------------------------------------------
__global__ void __launch_bounds__(256, 2) k_edge(
    const float* __restrict__ b1, const float* __restrict__ b2,
    float* __restrict__ out, int step)
{
    extern __shared__ __align__(1024) char sm[];
    uint32_t sb = smem_u32(sm);
    int tid = threadIdx.x, wid = tid >> 5, lane = tid & 31;
    int mbase = blockIdx.x * 128;

    CP16(sb + SM_W1H + tid*16, (const void*)(g_W1h + tid));
    CP16(sb + SM_W1H + 4096 + tid*16, (const void*)(g_W1h + 256 + tid));
    CP_COMMIT();
    {
        const uint4* src = g_W2h;
        uint32_t dst = sb + SM_B + tid*16;
        #pragma unroll
        for (int i = 0; i < 8; i++) CP16(dst + i*4096, (const void*)(src + tid + i*256));
    }
    CP_COMMIT();

    {
        float* d1 = (float*)(sm + SM_B1);
        float* d2 = (float*)(sm + SM_B2);
        d1[tid] = b1[tid]; d1[tid+256] = b1[tid+256];
        d2[tid] = b2[tid]; d2[tid+256] = b2[tid+256];
    }
    if (tid < 128) {
        int grow = mbase + tid;
        int bt = grow / Ec, e = grow - bt*Ec;
        int r  = e / (Nc-1), j = e - r*(Nc-1);
        int s  = j + (j >= r);
        float4 a = *(const float4*)(g_last + (bt*Nc + s)*Dc);
        float4 b = *(const float4*)(g_last + (bt*Nc + r)*Dc);
        uint4 pk;
        __half2 h0 = __floats2half2_rn(a.x, a.y);
        __half2 h1 = __floats2half2_rn(a.z, a.w);
        __half2 h2 = __floats2half2_rn(b.x, b.y);
        __half2 h3 = __floats2half2_rn(b.z, b.w);
        pk.x = *(uint32_t*)&h0; pk.y = *(uint32_t*)&h1;
        pk.z = *(uint32_t*)&h2; pk.w = *(uint32_t*)&h3;
        *(uint4*)(sm + SM_PMH + tid*16) = pk;
    }

    CP_WAIT(1);
    __syncthreads();

    int wm = wid & 3, wn = wid >> 2;
    int lrow = lane >> 2, lane4 = lane & 3;

    uint32_t aRow[2], bRow[2];
    #pragma unroll
    for (int mi = 0; mi < 2; mi++) {
        int row = wm*32 + mi*16 + (lane & 15);
        aRow[mi] = row*512 + ((row & 7) << 4);
    }
    #pragma unroll
    for (int njp = 0; njp < 2; njp++) {
        int row = wn*32 + njp*16 + ((lane >> 4) << 3) + (lane & 7);
        bRow[njp] = row*512 + ((row & 7) << 4);
    }
    uint32_t aSel = lane >> 4, bSel = (lane >> 3) & 1;

    float e0v[4], e1v[4]; int hookr[4];
    #pragma unroll
    for (int qq = 0; qq < 4; qq++) {
        int mi = qq >> 1, rg = qq & 1;
        int grow = mbase + wm*32 + mi*16 + rg*8 + lrow;
        int bt = grow / Ec, eG = grow - bt*Ec;
        e0v[qq] = g_edges[2*eG];
        e1v[qq] = g_edges[2*eG+1];
        int bb = bt >> 3, tg = bt & 7;
        hookr[qq] = ((step*TGc + tg)*Bc + bb)*Ec + eG;
    }
    int gs   = mbase + wm*32;
    int G0   = gs / 31;
    int bnd  = 31 - (gs - G0*31);

    const float* b2s = (const float*)(sm + SM_B2);

    #pragma unroll
    for (int e = 0; e < 2; e++) {
        {
            int m0 = wid * 16;
            uint32_t a0, a1;
            LDMX2(a0, a1, sb + SM_PMH + (m0 + (lane & 15))*16);
            const float* b1e = (const float*)(sm + SM_B1) + e*256;
            #pragma unroll
            for (int nc = 0; nc < 8; nc++) {
                uint32_t bf[4];
                LDMX4(bf[0], bf[1], bf[2], bf[3],
                      sb + SM_W1H + e*4096 + (nc*32 + lane)*16);
                #pragma unroll
                for (int c = 0; c < 4; c++) {
                    float acc[4] = {0.f, 0.f, 0.f, 0.f};
                    MMA16808(acc, a0, a1, bf[c]);
                    int col = nc*32 + c*8 + (lane & 3)*2;
                    float bx = b1e[col], by = b1e[col+1];
                    __half2 v0 = __floats2half2_rn(fmaxf(acc[0]+bx, 0.f), fmaxf(acc[1]+by, 0.f));
                    __half2 v1 = __floats2half2_rn(fmaxf(acc[2]+bx, 0.f), fmaxf(acc[3]+by, 0.f));
                    int r0 = m0 + (lane >> 2), r1 = r0 + 8;
                    *(__half2*)(sm + SM_A + swb(r0, col)) = v0;
                    *(__half2*)(sm + SM_A + swb(r1, col)) = v1;
                }
            }
        }
        CP_WAIT(0);
        __syncthreads();

        #pragma unroll
        for (int q = 0; q < 4; q++) {
            float acc[2][4][4];
            gemm_q(acc, sb + SM_A, sb + SM_B, aRow, bRow, aSel, bSel);
            __syncthreads();

            if (q < 3 || e == 0) {
                int ne = (q < 3) ? e : 1;
                int nq = (q < 3) ? q + 1 : 0;
                const uint4* src = g_W2h + ne*8192 + nq*2048;
                uint32_t dst = sb + SM_B + tid*16;
                #pragma unroll
                for (int i = 0; i < 8; i++) CP16(dst + i*4096, (const void*)(src + tid + i*256));
            }
            CP_COMMIT();

            #pragma unroll
            for (int nj = 0; nj < 4; nj++) {
                int cg = q*64 + wn*32 + nj*8 + lane4*2;
                float bx = b2s[e*256 + cg], by = b2s[e*256 + cg + 1];
                float pA0 = 0.f, pA1 = 0.f, pB0 = 0.f, pB1 = 0.f;
                #pragma unroll
                for (int mi = 0; mi < 2; mi++)
                    #pragma unroll
                    for (int rg = 0; rg < 2; rg++) {
                        int ridx = mi*2 + rg;
                        float sc = e ? e1v[ridx] : e0v[ridx];
                        float v0 = fmaxf(acc[mi][nj][rg*2]   + bx, 0.f) * sc;
                        float v1 = fmaxf(acc[mi][nj][rg*2+1] + by, 0.f) * sc;
                        if (e == 1)
                            *(float2*)(out + OFF_HOOK + (size_t)hookr[ridx]*Hc + cg) =
                                make_float2(v0, v1);
                        int rel = mi*16 + rg*8 + lrow;
                        if (rel < bnd) { pA0 += v0; pA1 += v1; }
                        else           { pB0 += v0; pB1 += v1; }
                    }
                #pragma unroll
                for (int d = 4; d <= 16; d <<= 1) {
                    pA0 += __shfl_xor_sync(0xffffffffu, pA0, d);
                    pA1 += __shfl_xor_sync(0xffffffffu, pA1, d);
                    pB0 += __shfl_xor_sync(0xffffffffu, pB0, d);
                    pB1 += __shfl_xor_sync(0xffffffffu, pB1, d);
                }
                if (lane < 4) {
                    atomicAdd(g_agg + (size_t)G0*Hc + cg,         pA0);
                    atomicAdd(g_agg + (size_t)G0*Hc + cg + 1,     pA1);
                    atomicAdd(g_agg + (size_t)(G0+1)*Hc + cg,     pB0);
                    atomicAdd(g_agg + (size_t)(G0+1)*Hc + cg + 1, pB1);
                }
            }
            CP_WAIT(0);
            __syncthreads();
        }
    }
}

// ---------------------------------------------------------------------------
// Node MLP v8 (HMMA, 6-buffer / depth-5 pipelined weight stream)
// ---------------------------------------------------------------------------
#define NBUF 6
static __device__ __forceinline__ uint32_t nbuf_off(int q) {
    return (uint32_t)((q % NBUF) * 12288);
}
static __device__ __forceinline__ void nprefetch(int q, uint32_t dstB, int tid) {
    const char* src = (q < 17)
        ? ((const char*)g_Wo1h4 + q*8192)
        : ((const char*)g_Wo2h4 + (q-17)*8192);
    uint32_t dst = dstB + tid*48;
    const char* s = src + tid*32;
    CP16(dst, s);
    CP16(dst + 16, s + 16);
}

static __device__ __forceinline__ void node_chunk(
    float (&acc)[4][4], uint32_t aBase, int q, uint32_t bBase, int lane, int wn)
{
    uint32_t a0, a1, a2, a3;
    LDMX4(a0, a1, a2, a3, aBase + (lane & 15)*560 + q*32 + (lane >> 4)*16);
    #pragma unroll
    for (int njp = 0; njp < 2; njp++) {
        uint32_t row = wn + njp*16 + ((lane >> 4) << 3) + (lane & 7);
        uint32_t b0, b1, b2, b3;
        LDMX4(b0, b1, b2, b3, bBase + row*48 + ((lane >> 3) & 1)*16);
        MMA16816(acc[njp*2],   a0, a1, a2, a3, b0, b1);
        MMA16816(acc[njp*2+1], a0, a1, a2, a3, b2, b3);
    }
}

__global__ void __launch_bounds__(256) k_node(
    const float* __restrict__ bo1, const float* __restrict__ bo2,
    const float* __restrict__ Wo3, const float* __restrict__ bo3,
    float* __restrict__ out, int step)
{
    extern __shared__ __align__(16) char nsm[];
    uint32_t sb = smem_u32(nsm);
    float* aug2S = (float*)(nsm + NA_AUG2);
    float* lastS = (float*)(nsm + NA_LAST);
    float* wo3S  = (float*)(nsm + NA_WO3);
    float* bo1S  = (float*)(nsm + NA_BO);
    float* bo2S  = (float*)(nsm + NA_BO + 1024);

    int tid = threadIdx.x, wid = tid >> 5, lane = tid & 31;
    int base_row = blockIdx.x * 16;
    int wn = wid * 32;

    // prologue: prefetch chunks 0..4, one ordered commit group each
    #pragma unroll
    for (int q = 0; q < 5; q++) {
        nprefetch(q, sb + NA_B + nbuf_off(q), tid);
        CP_COMMIT();
    }

    bo1S[tid] = bo1[tid];
    bo2S[tid] = bo2[tid];
    #pragma unroll
    for (int i = 0; i < 4; i++) wo3S[tid + i*256] = Wo3[tid + i*256];

    // aug -> fp16 A tile; zero g_agg; last
    #pragma unroll
    for (int rr = 0; rr < 2; rr++) {
        int row = wid*2 + rr;
        float* src = g_agg + (size_t)(base_row + row)*Hc + lane*8;
        float4 v0 = *(float4*)src, v1 = *(float4*)(src + 4);
        __half2 h0 = __floats2half2_rn(v0.x, v0.y);
        __half2 h1 = __floats2half2_rn(v0.z, v0.w);
        __half2 h2 = __floats2half2_rn(v1.x, v1.y);
        __half2 h3 = __floats2half2_rn(v1.z, v1.w);
        uint2 w0, w1;
        w0.x = *(uint32_t*)&h0; w0.y = *(uint32_t*)&h1;
        w1.x = *(uint32_t*)&h2; w1.y = *(uint32_t*)&h3;
        char* dst = nsm + NA_A + row*560 + 8 + lane*16;
        *(uint2*)dst = w0;
        *(uint2*)(dst + 8) = w1;
        float4 z = make_float4(0.f, 0.f, 0.f, 0.f);
        *(float4*)src = z; *(float4*)(src + 4) = z;
    }
    if (tid < 64) {
        int r = tid >> 2, d = tid & 3;
        float v = g_last[(base_row + r)*Dc + d];
        lastS[r*4 + d] = v;
        *(__half*)(nsm + NA_A + r*560 + d*2) = __float2half(v);
    }
    if (tid < 16) {   // zero K pad [260,272)
        char* p = nsm + NA_A + tid*560 + 520;
        *(uint2*)p = make_uint2(0u, 0u);
        *(uint2*)(p + 8) = make_uint2(0u, 0u);
        *(uint2*)(p + 16) = make_uint2(0u, 0u);
    }

    // ---- layer 1: chunks 0..16 (depth-5; CP_WAIT(4) => chunk q complete) ----
    float acc[4][4];
    #pragma unroll
    for (int t = 0; t < 4; t++)
        #pragma unroll
        for (int c = 0; c < 4; c++) acc[t][c] = 0.f;

    for (int q = 0; q < 17; q++) {
        CP_WAIT(4);
        __syncthreads();
        if (q + 5 < 33) nprefetch(q + 5, sb + NA_B + nbuf_off(q + 5), tid);
        CP_COMMIT();   // empty at the tail; keeps group numbering aligned
        node_chunk(acc, sb + NA_A, q, sb + NA_B + nbuf_off(q), lane, wn);
    }
    // epilogue 1: bias+relu -> H fp16
    {
        int r0 = lane >> 2, r1 = r0 + 8;
        #pragma unroll
        for (int t = 0; t < 4; t++) {
            int c = wn + t*8 + (lane & 3)*2;
            float bx = bo1S[c], by = bo1S[c+1];
            __half2 p0 = __floats2half2_rn(fmaxf(acc[t][0]+bx, 0.f), fmaxf(acc[t][1]+by, 0.f));
            __half2 p1 = __floats2half2_rn(fmaxf(acc[t][2]+bx, 0.f), fmaxf(acc[t][3]+by, 0.f));
            *(__half2*)(nsm + NA_H + r0*560 + c*2) = p0;
            *(__half2*)(nsm + NA_H + r1*560 + c*2) = p1;
        }
    }
    __syncthreads();

    // ---- layer 2: chunks 17..32 ----
    #pragma unroll
    for (int t = 0; t < 4; t++)
        #pragma unroll
        for (int c = 0; c < 4; c++) acc[t][c] = 0.f;

    for (int q2 = 0; q2 < 16; q2++) {
        int q = 17 + q2;
        CP_WAIT(4);
        __syncthreads();
        if (q + 5 < 33) nprefetch(q + 5, sb + NA_B + nbuf_off(q + 5), tid);
        CP_COMMIT();
        node_chunk(acc, sb + NA_H, q2, sb + NA_B + nbuf_off(q), lane, wn);
    }
    // epilogue 2: bias+relu -> aug2 fp32
    {
        int r0 = lane >> 2, r1 = r0 + 8;
        #pragma unroll
        for (int t = 0; t < 4; t++) {
            int c = wn + t*8 + (lane & 3)*2;
            float bx = bo2S[c], by = bo2S[c+1];
            aug2S[r0*264 + c]     = fmaxf(acc[t][0] + bx, 0.f);
            aug2S[r0*264 + c + 1] = fmaxf(acc[t][1] + by, 0.f);
            aug2S[r1*264 + c]     = fmaxf(acc[t][2] + bx, 0.f);
            aug2S[r1*264 + c + 1] = fmaxf(acc[t][3] + by, 0.f);
        }
    }
    __syncthreads();

    // ---- layer 3 (256->4) + residual + writes ----
    if (tid < 64) {
        int n = tid >> 2, d = tid & 3;
        float v = bo3[d];
        #pragma unroll 8
        for (int cc = 0; cc < Hc; cc++)
            v += aug2S[n*264 + cc] * wo3S[cc*Dc + d];
        float nl = lastS[n*4 + d] + v;
        int grow = base_row + n;
        g_last[grow*Dc + d] = nl;
        int bt = grow >> 5, gn = grow & 31;
        int b = bt >> 3, tg = bt & 7;
        int t = tg*Pc + step;
        if (t < Tc - 1)
            out[((b*Nc + gn)*(Tc-1) + t)*Dc + d] = nl;
    }
}

// ---------------------------------------------------------------------------
extern "C" void kernel_launch(void* const* d_in, const int* in_sizes, int n_in,
                              void* d_out, int out_size)
{
    const float* inputs    = (const float*)d_in[0];
    const float* rel_graph = (const float*)d_in[1];
    const float* W1  = (const float*)d_in[2];
    const float* b1  = (const float*)d_in[3];
    const float* W2  = (const float*)d_in[4];
    const float* b2  = (const float*)d_in[5];
    const float* Wo1 = (const float*)d_in[6];
    const float* bo1 = (const float*)d_in[7];
    const float* Wo2 = (const float*)d_in[8];
    const float* bo2 = (const float*)d_in[9];
    const float* Wo3 = (const float*)d_in[10];
    const float* bo3 = (const float*)d_in[11];
    const float* gumbel = (const float*)d_in[14];
    float* out = (float*)d_out;

    cudaFuncSetAttribute(k_edge, cudaFuncAttributeMaxDynamicSharedMemorySize, SMEM_TOTAL);
    cudaFuncSetAttribute(k_node, cudaFuncAttributeMaxDynamicSharedMemorySize, NSM_TOTAL);

    k_setup<<<128, 256>>>(rel_graph, gumbel, inputs, out);
    k_prep<<<64, 256>>>(W2, W1, Wo1, Wo2);
    for (int p = 0; p < Pc; p++) {
        k_edge<<<ROWS_E/128, 256, SMEM_TOTAL>>>(b1, b2, out, p);
        k_node<<<128, 256, NSM_TOTAL>>>(bo1, bo2, Wo3, bo3, out, p);
    }
}